// round 9
// baseline (speedup 1.0000x reference)
#include <cuda_runtime.h>
#include <math.h>

#define BB 16
#define CC 64
#define NN 2000
#define OCC 64
#define NP 2048   // padded size for bitonic sort
#define TILE 128
#define NT 16     // NT*TILE = 2048 >= NN
#define KP 2048   // prefix index space

// ---------------- scratch (no allocations allowed) ----------------
__device__ float  g_h[BB * NN * OCC];    // h[b][n][c]
__device__ float  g_f1[BB * NN];
__device__ float  g_f2[BB * NN];
__device__ float  g_f2s[BB * NP];        // sorted f2 (ascending), padded +inf
__device__ int    g_perm[BB * NP];       // sorted rank -> original j
__device__ float2 g_pre[BB * KP * OCC];  // within-tile excl prefix {S=exp(.01 f2)*h, B=exp(f2)*h}
__device__ float2 g_preZ[BB * KP];       // within-tile excl prefix of weights {S,B}
__device__ float2 g_ts[BB * NT * OCC];   // per-tile sums {S,B}
__device__ float2 g_tsZ[BB * NT];        // per-tile weight sums {S,B}

// ---------------- kernel A: h = x^T W ; f1 = x^T (W a1), f2 = x^T (W a2) ----------------
// grid (25, 16), block 256; 80 n-columns per block; 5n x 4c register tile per thread
__global__ void k_h(const float* __restrict__ inp, const float* __restrict__ W,
                    const float* __restrict__ a) {
    __shared__ float xs[80][CC + 1];     // [nl][k]
    __shared__ float Ws[CC][OCC + 1];    // [k][c]
    __shared__ float as_[128];
    __shared__ float wa1[CC], wa2[CC];
    int b = blockIdx.y;
    int n0 = blockIdx.x * 80;
    int tid = threadIdx.x;

    for (int t = tid; t < CC * OCC; t += 256)
        Ws[t >> 6][t & 63] = W[t];
    for (int t = tid; t < 80 * CC; t += 256) {
        int c = t / 80, nl = t % 80;
        xs[nl][c] = inp[(b * CC + c) * NN + n0 + nl];
    }
    if (tid < 128) as_[tid] = a[tid];
    __syncthreads();

    if (tid < 128) {   // wa1 = W @ a1, wa2 = W @ a2
        int c = tid & 63;
        const float* av = as_ + (tid >> 6) * 64;
        float s = 0.f;
#pragma unroll
        for (int oc = 0; oc < 64; oc++)
            s = fmaf(Ws[c][oc], av[oc], s);
        if (tid < 64) wa1[c] = s; else wa2[c] = s;
    }

    // ---- register-tiled GEMM: thread owns rows nl0..nl0+4, cols c0..c0+3 ----
    {
        int cg = tid & 15, ng = tid >> 4;
        int c0 = cg * 4, nl0 = ng * 5;
        float4 acc0 = make_float4(0.f, 0.f, 0.f, 0.f);
        float4 acc1 = acc0, acc2 = acc0, acc3 = acc0, acc4 = acc0;
#pragma unroll 8
        for (int k = 0; k < CC; k++) {
            float w0 = Ws[k][c0], w1 = Ws[k][c0 + 1], w2 = Ws[k][c0 + 2], w3 = Ws[k][c0 + 3];
            float x0 = xs[nl0][k], x1 = xs[nl0 + 1][k], x2 = xs[nl0 + 2][k],
                  x3 = xs[nl0 + 3][k], x4 = xs[nl0 + 4][k];
            acc0.x = fmaf(x0, w0, acc0.x); acc0.y = fmaf(x0, w1, acc0.y);
            acc0.z = fmaf(x0, w2, acc0.z); acc0.w = fmaf(x0, w3, acc0.w);
            acc1.x = fmaf(x1, w0, acc1.x); acc1.y = fmaf(x1, w1, acc1.y);
            acc1.z = fmaf(x1, w2, acc1.z); acc1.w = fmaf(x1, w3, acc1.w);
            acc2.x = fmaf(x2, w0, acc2.x); acc2.y = fmaf(x2, w1, acc2.y);
            acc2.z = fmaf(x2, w2, acc2.z); acc2.w = fmaf(x2, w3, acc2.w);
            acc3.x = fmaf(x3, w0, acc3.x); acc3.y = fmaf(x3, w1, acc3.y);
            acc3.z = fmaf(x3, w2, acc3.z); acc3.w = fmaf(x3, w3, acc3.w);
            acc4.x = fmaf(x4, w0, acc4.x); acc4.y = fmaf(x4, w1, acc4.y);
            acc4.z = fmaf(x4, w2, acc4.z); acc4.w = fmaf(x4, w3, acc4.w);
        }
        float4* hrow = (float4*)(g_h + (size_t)(b * NN + n0 + nl0) * OCC + c0);
        size_t rs = OCC / 4;
        hrow[0] = acc0; hrow[rs] = acc1; hrow[2 * rs] = acc2;
        hrow[3 * rs] = acc3; hrow[4 * rs] = acc4;
    }
    __syncthreads();

    if (tid < 80) {   // f1/f2 dot products
        float s1 = 0.f, s2 = 0.f;
#pragma unroll
        for (int k = 0; k < CC; k++) {
            float xv = xs[tid][k];
            s1 = fmaf(xv, wa1[k], s1);
            s2 = fmaf(xv, wa2[k], s2);
        }
        g_f1[b * NN + n0 + tid] = s1;
        g_f2[b * NN + n0 + tid] = s2;
    }
}

// ---------------- kernel C: per-batch bitonic sort of f2 (ascending) ----------------
__global__ void k_sort() {
    __shared__ float key[NP];
    __shared__ int   idx[NP];
    int b = blockIdx.x, tid = threadIdx.x;

    for (int i = tid; i < NP; i += 1024) {
        key[i] = (i < NN) ? g_f2[b * NN + i] : __int_as_float(0x7f800000);
        idx[i] = i;
    }
    __syncthreads();

    for (int kk = 2; kk <= NP; kk <<= 1) {
        for (int j = kk >> 1; j > 0; j >>= 1) {
#pragma unroll
            for (int half = 0; half < 2; half++) {
                int i = tid + half * 1024;
                int ixj = i ^ j;
                if (ixj > i) {
                    bool up = ((i & kk) == 0);
                    float ki = key[i], kx = key[ixj];
                    bool sw = up ? (ki > kx) : (ki < kx);
                    if (sw) {
                        key[i] = kx; key[ixj] = ki;
                        int t = idx[i]; idx[i] = idx[ixj]; idx[ixj] = t;
                    }
                }
            }
            __syncthreads();
        }
    }
    for (int i = tid; i < NP; i += 1024) {
        g_f2s[b * NP + i] = key[i];
        g_perm[b * NP + i] = idx[i];
    }
}

// ---------------- kernel D: within-tile exclusive prefixes + tile sums ----------------
// grid (NT, BB), block 256: 4 segments of 32 rows x 64 channels
#define SEG 32
__global__ void k_tile() {
    __shared__ float  hs[TILE][OCC];
    __shared__ float  wS[TILE], wB[TILE];
    __shared__ int    pidx[TILE];
    __shared__ float2 segsum[4][OCC];
    __shared__ float2 segoff[4][OCC];
    __shared__ float2 segsumZ[4], segoffZ[4];
    int b = blockIdx.y, t = blockIdx.x, tid = threadIdx.x;
    int r0 = t * TILE;

    if (tid < TILE) {
        int gp = r0 + tid;
        if (gp < NN) {
            float f = g_f2s[b * NP + gp];
            wS[tid] = expf(0.01f * f);
            wB[tid] = expf(f);
            pidx[tid] = g_perm[b * NP + gp];
        } else {
            wS[tid] = 0.f; wB[tid] = 0.f; pidx[tid] = 0;
        }
    }
    __syncthreads();
    for (int x = tid; x < TILE * 16; x += 256) {
        int r = x >> 4, q = x & 15;
        reinterpret_cast<float4*>(hs[r])[q] =
            reinterpret_cast<const float4*>(g_h + (size_t)(b * NN + pidx[r]) * OCC)[q];
    }
    __syncthreads();

    int c = tid & 63, seg = tid >> 6;
    int rbeg = seg * SEG;

    {
        float aS = 0.f, aB = 0.f;
#pragma unroll 4
        for (int r = 0; r < SEG; r++) {
            int gr = rbeg + r;
            float hv = hs[gr][c];
            aS = fmaf(wS[gr], hv, aS);
            aB = fmaf(wB[gr], hv, aB);
        }
        segsum[seg][c] = make_float2(aS, aB);
    }
    if (tid < 4) {
        int rb = tid * SEG;
        float zS = 0.f, zB = 0.f;
#pragma unroll 4
        for (int r = 0; r < SEG; r++) { zS += wS[rb + r]; zB += wB[rb + r]; }
        segsumZ[tid] = make_float2(zS, zB);
    }
    __syncthreads();

    if (tid < 64) {
        float aS = 0.f, aB = 0.f;
#pragma unroll
        for (int s = 0; s < 4; s++) {
            segoff[s][tid] = make_float2(aS, aB);
            float2 v = segsum[s][tid];
            aS += v.x; aB += v.y;
        }
        g_ts[(b * NT + t) * OCC + tid] = make_float2(aS, aB);
    } else if (tid == 64) {
        float zS = 0.f, zB = 0.f;
#pragma unroll
        for (int s = 0; s < 4; s++) {
            segoffZ[s] = make_float2(zS, zB);
            float2 v = segsumZ[s];
            zS += v.x; zB += v.y;
        }
        g_tsZ[b * NT + t] = make_float2(zS, zB);
    }
    __syncthreads();

    {
        float2 o = segoff[seg][c];
        float aS = o.x, aB = o.y;
#pragma unroll 4
        for (int r = 0; r < SEG; r++) {
            int gr = rbeg + r;
            g_pre[(size_t)(b * KP + r0 + gr) * OCC + c] = make_float2(aS, aB);
            float hv = hs[gr][c];
            aS = fmaf(wS[gr], hv, aS);
            aB = fmaf(wB[gr], hv, aB);
        }
    }
    if (tid < 4) {
        int rb = tid * SEG;
        float2 o = segoffZ[tid];
        float zS = o.x, zB = o.y;
#pragma unroll 4
        for (int r = 0; r < SEG; r++) {
            g_preZ[b * KP + r0 + rb + r] = make_float2(zS, zB);
            zS += wS[rb + r]; zB += wB[rb + r];
        }
    }
}

// ---------------- kernel E: search + combine + relu + transpose (40 rows / block) ----------------
// grid (50, 16), block (64, 8) = 512
__global__ void __launch_bounds__(512, 2) k_out(float* __restrict__ out) {
    __shared__ float  fs[NN];
    __shared__ float  sm[40][OCC + 1];
    __shared__ float2 tstage[NT][OCC];    // staged g_ts (parallel loads)
    __shared__ float2 to[NT + 1][OCC];    // exclusive tile offsets (+ total)
    __shared__ float2 ztstage[NT];
    __shared__ float  zpreS[NT + 1], zpreB[NT + 1];
    __shared__ int    kks[40];
    __shared__ float  f1s[40];
    __shared__ float4 rinfo[40];          // {A, aa, rden, pad}

    int b = blockIdx.y;
    int i0 = blockIdx.x * 40;
    int c = threadIdx.x, il = threadIdx.y;
    int tid = il * 64 + c;

    // ---- parallel staging: everything global -> smem with max MLP ----
    for (int x = tid; x < NN; x += 512)
        fs[x] = g_f2s[b * NP + x];
    {
        int ta = tid >> 6, ca = tid & 63;
        tstage[ta][ca] = g_ts[(b * NT + ta) * OCC + ca];
        int t2 = tid + 512;
        int tb = t2 >> 6, cb = t2 & 63;
        tstage[tb][cb] = g_ts[(b * NT + tb) * OCC + cb];
    }
    if (tid < NT) ztstage[tid] = g_tsZ[b * NT + tid];
    if (tid < 40) f1s[tid] = g_f1[b * NN + i0 + tid];
    __syncthreads();

    // ---- prefix over smem-staged tile sums (LDS-latency chains) ----
    if (tid < 64) {
        float aS = 0.f, aB = 0.f;
#pragma unroll
        for (int t2 = 0; t2 < NT; t2++) {
            to[t2][tid] = make_float2(aS, aB);
            float2 v = tstage[t2][tid];
            aS += v.x; aB += v.y;
        }
        to[NT][tid] = make_float2(aS, aB);
    } else if (tid == 64) {
        float aS = 0.f, aB = 0.f;
#pragma unroll
        for (int t2 = 0; t2 < NT; t2++) {
            zpreS[t2] = aS; zpreB[t2] = aB;
            float2 z = ztstage[t2];
            aS += z.x; aB += z.y;
        }
        zpreS[NT] = aS; zpreB[NT] = aB;
    }
    __syncthreads();

    // ---- per-row stage: search + all row-only math ----
    if (tid < 40) {
        float f1v = f1s[tid];
        float th = -f1v;
        int lo = 0, hi = NN;              // lower_bound: first idx with f2 >= -f1
        while (lo < hi) {
            int mid = (lo + hi) >> 1;
            if (fs[mid] < th) lo = mid + 1; else hi = mid;
        }
        int k = lo, t = lo >> 7;
        float2 preZ = g_preZ[b * KP + k];
        float pZS = zpreS[t] + preZ.x;
        float pZB = zpreB[t] + preZ.y;
        float A  = expf(f1v);
        float aa = expf(0.01f * f1v);
        float den = A * (zpreB[NT] - pZB) + aa * pZS;
        kks[tid] = k;
        rinfo[tid] = make_float4(A, aa, 1.f / den, 0.f);
    }
    __syncthreads();

    // ---- combine: prefetch all 5 g_pre loads (MLP=5), then compute ----
    {
        float totB = to[NT][c].y;
        int kk[5];
#pragma unroll
        for (int g = 0; g < 5; g++) kk[g] = kks[g * 8 + il];
        float2 pv[5];
#pragma unroll
        for (int g = 0; g < 5; g++)
            pv[g] = g_pre[(size_t)(b * KP + kk[g]) * OCC + c];
#pragma unroll
        for (int g = 0; g < 5; g++) {
            int rl = g * 8 + il;
            float4 ri = rinfo[rl];
            float2 tov = to[kk[g] >> 7][c];
            float pS = tov.x + pv[g].x;
            float pB = tov.y + pv[g].y;
            float num = ri.x * (totB - pB) + ri.y * pS;
            sm[rl][c] = fmaxf(num * ri.z, 0.f);
        }
    }
    __syncthreads();

    // ---- transpose-store, incremental index math ----
    {
        int c2 = tid / 40, i2 = tid % 40;
#pragma unroll
        for (int g = 0; g < 5; g++) {
            out[(b * OCC + c2) * NN + i0 + i2] = sm[i2][c2];
            i2 += 32; c2 += 12;            // +512 = +12*40 + 32
            if (i2 >= 40) { i2 -= 40; c2 += 1; }
        }
    }
}

// ---------------- launch ----------------
extern "C" void kernel_launch(void* const* d_in, const int* in_sizes, int n_in,
                              void* d_out, int out_size) {
    const float* inp = (const float*)d_in[0];   // (16, 64, 2000)
    const float* W   = (const float*)d_in[1];   // (64, 64)
    const float* a   = (const float*)d_in[2];   // (128, 1)
    // d_in[3] = GL : unused (softmax output strictly positive -> adjacency mask is a no-op)
    float* out = (float*)d_out;                 // (16, 64, 2000)

    k_h   <<<dim3(25, BB), 256>>>(inp, W, a);
    k_sort<<<BB, 1024>>>();
    k_tile<<<dim3(NT, BB), 256>>>();
    k_out <<<dim3(50, BB), dim3(64, 8)>>>(out);
}

// round 10
// speedup vs baseline: 1.2872x; 1.2872x over previous
#include <cuda_runtime.h>
#include <math.h>

#define BB 16
#define CC 64
#define NN 2000
#define OCC 64
#define NP 2048   // padded size for bitonic sort
#define TILE 128
#define NT 16     // NT*TILE = 2048 >= NN
#define KP 2048   // prefix index space

typedef unsigned long long u64;
typedef unsigned int u32;

// ---------------- scratch (no allocations allowed) ----------------
__device__ float  g_h[BB * NN * OCC];    // h[b][n][c]
__device__ float  g_f1[BB * NN];
__device__ float  g_f2[BB * NN];
__device__ float  g_f2s[BB * NP];        // sorted f2 (ascending)
__device__ int    g_perm[BB * NP];       // sorted rank -> original j
__device__ float2 g_pre[BB * KP * OCC];  // within-tile excl prefix {S=exp(.01 f2)*h, B=exp(f2)*h}
__device__ float2 g_preZ[BB * KP];       // within-tile excl prefix of weights {S,B}
__device__ float2 g_ts[BB * NT * OCC];   // per-tile sums {S,B}
__device__ float2 g_tsZ[BB * NT];        // per-tile weight sums {S,B}

// ---------------- kernel A: h = x^T W ; f1 = x^T (W a1), f2 = x^T (W a2) ----------------
// grid (25, 16), block 128; 80 n-columns per block; 5n x 8c register tile per thread
__global__ void k_h(const float* __restrict__ inp, const float* __restrict__ W,
                    const float* __restrict__ a) {
    __shared__ float xs[80][CC + 1];     // [nl][k]
    __shared__ float Ws[CC][OCC + 1];    // [k][c]
    __shared__ float as_[128];
    __shared__ float wa1[CC], wa2[CC];
    int b = blockIdx.y;
    int n0 = blockIdx.x * 80;
    int tid = threadIdx.x;               // 0..127

    for (int t = tid; t < CC * OCC; t += 128)
        Ws[t >> 6][t & 63] = W[t];
    for (int t = tid; t < 80 * CC; t += 128) {
        int c = t / 80, nl = t % 80;
        xs[nl][c] = inp[(b * CC + c) * NN + n0 + nl];
    }
    if (tid < 128) as_[tid] = a[tid];
    __syncthreads();

    {   // wa1 = W @ a1, wa2 = W @ a2 (128 threads)
        int c = tid & 63;
        const float* av = as_ + (tid >> 6) * 64;
        float s = 0.f;
#pragma unroll
        for (int oc = 0; oc < 64; oc++)
            s = fmaf(Ws[c][oc], av[oc], s);
        if (tid < 64) wa1[c] = s; else wa2[c] = s;
    }

    // ---- register-tiled GEMM: thread owns rows nl0..nl0+4, cols c0..c0+7 ----
    {
        int cg = tid & 7, ng = tid >> 3;   // 8 channel groups x 16 row groups
        int c0 = cg * 8, nl0 = ng * 5;
        float4 accA[5], accB[5];
#pragma unroll
        for (int r = 0; r < 5; r++) {
            accA[r] = make_float4(0.f, 0.f, 0.f, 0.f);
            accB[r] = make_float4(0.f, 0.f, 0.f, 0.f);
        }
#pragma unroll 4
        for (int k = 0; k < CC; k++) {
            float w0 = Ws[k][c0],     w1 = Ws[k][c0 + 1], w2 = Ws[k][c0 + 2], w3 = Ws[k][c0 + 3];
            float w4 = Ws[k][c0 + 4], w5 = Ws[k][c0 + 5], w6 = Ws[k][c0 + 6], w7 = Ws[k][c0 + 7];
#pragma unroll
            for (int r = 0; r < 5; r++) {
                float xv = xs[nl0 + r][k];
                accA[r].x = fmaf(xv, w0, accA[r].x); accA[r].y = fmaf(xv, w1, accA[r].y);
                accA[r].z = fmaf(xv, w2, accA[r].z); accA[r].w = fmaf(xv, w3, accA[r].w);
                accB[r].x = fmaf(xv, w4, accB[r].x); accB[r].y = fmaf(xv, w5, accB[r].y);
                accB[r].z = fmaf(xv, w6, accB[r].z); accB[r].w = fmaf(xv, w7, accB[r].w);
            }
        }
#pragma unroll
        for (int r = 0; r < 5; r++) {
            float4* hrow = (float4*)(g_h + (size_t)(b * NN + n0 + nl0 + r) * OCC + c0);
            hrow[0] = accA[r];
            hrow[1] = accB[r];
        }
    }
    __syncthreads();

    if (tid < 80) {   // f1/f2 dot products
        float s1 = 0.f, s2 = 0.f;
#pragma unroll
        for (int k = 0; k < CC; k++) {
            float xv = xs[tid][k];
            s1 = fmaf(xv, wa1[k], s1);
            s2 = fmaf(xv, wa2[k], s2);
        }
        g_f1[b * NN + n0 + tid] = s1;
        g_f2[b * NN + n0 + tid] = s2;
    }
}

// ---------------- kernel C: per-batch bitonic sort (register + shfl hybrid) ----------------
// 2048 elems as u64 (sortable_key << 32 | idx); 2 elems/thread; j<=32 stages in registers.
__device__ __forceinline__ void reg_stage(u64& v0, u64& v1, int tid, int k, int jhi) {
    bool up = (((2 * tid) & k) == 0);
#pragma unroll
    for (int j = 32; j >= 2; j >>= 1) {
        if (j > jhi) continue;
        int h = j >> 1;
        u64 p0 = __shfl_xor_sync(0xffffffffu, v0, h);
        u64 p1 = __shfl_xor_sync(0xffffffffu, v1, h);
        bool takeMin = (((tid & h) == 0) == up);
        u64 lo0 = v0 < p0 ? v0 : p0, hi0 = v0 < p0 ? p0 : v0;
        u64 lo1 = v1 < p1 ? v1 : p1, hi1 = v1 < p1 ? p1 : v1;
        v0 = takeMin ? lo0 : hi0;
        v1 = takeMin ? lo1 : hi1;
    }
    // j == 1: in-thread
    if ((v0 > v1) == up) { u64 t = v0; v0 = v1; v1 = t; }
}

__global__ void k_sort() {
    __shared__ u64 s[NP];                 // 16 KB
    int b = blockIdx.x, tid = threadIdx.x;   // 1024 threads

    // load + pack (2 elems per thread, register-resident)
    u64 v0, v1;
    {
        int i0 = 2 * tid, i1 = 2 * tid + 1;
        if (i0 < NN) {
            u32 u = __float_as_uint(g_f2[b * NN + i0]);
            u = (u & 0x80000000u) ? ~u : (u ^ 0x80000000u);
            v0 = ((u64)u << 32) | (u32)i0;
        } else v0 = ~0ull;
        if (i1 < NN) {
            u32 u = __float_as_uint(g_f2[b * NN + i1]);
            u = (u & 0x80000000u) ? ~u : (u ^ 0x80000000u);
            v1 = ((u64)u << 32) | (u32)i1;
        } else v1 = ~0ull;
    }

    // k = 2..64 entirely in registers (no barriers)
#pragma unroll
    for (int k = 2; k <= 64; k <<= 1)
        reg_stage(v0, v1, tid, k, k >> 1);

    s[2 * tid] = v0; s[2 * tid + 1] = v1;
    __syncthreads();

    // k = 128..2048: smem stages for j>=64, register tail for j<=32
    for (int k = 128; k <= 2048; k <<= 1) {
        for (int j = k >> 1; j >= 64; j >>= 1) {
#pragma unroll
            for (int half = 0; half < 2; half++) {
                int i = tid + half * 1024;
                int ixj = i ^ j;
                if (ixj > i) {
                    bool up = ((i & k) == 0);
                    u64 a = s[i], x = s[ixj];
                    if (up ? (a > x) : (a < x)) { s[i] = x; s[ixj] = a; }
                }
            }
            __syncthreads();
        }
        v0 = s[2 * tid]; v1 = s[2 * tid + 1];
        reg_stage(v0, v1, tid, k, 32);
        s[2 * tid] = v0; s[2 * tid + 1] = v1;
        __syncthreads();
    }

    // unpack + write
#pragma unroll
    for (int half = 0; half < 2; half++) {
        int i = tid + half * 1024;
        u64 v = s[i];
        u32 hi = (u32)(v >> 32);
        hi = (hi & 0x80000000u) ? (hi ^ 0x80000000u) : ~hi;
        g_f2s[b * NP + i] = __uint_as_float(hi);
        g_perm[b * NP + i] = (int)(v & 0xffffffffu);
    }
}

// ---------------- kernel D: within-tile exclusive prefixes + tile sums ----------------
// grid (NT, BB), block 256: 4 segments of 32 rows x 64 channels
#define SEG 32
__global__ void k_tile() {
    __shared__ float  hs[TILE][OCC];
    __shared__ float  wS[TILE], wB[TILE];
    __shared__ int    pidx[TILE];
    __shared__ float2 segsum[4][OCC];
    __shared__ float2 segoff[4][OCC];
    __shared__ float2 segsumZ[4], segoffZ[4];
    int b = blockIdx.y, t = blockIdx.x, tid = threadIdx.x;
    int r0 = t * TILE;

    if (tid < TILE) {
        int gp = r0 + tid;
        if (gp < NN) {
            float f = g_f2s[b * NP + gp];
            wS[tid] = expf(0.01f * f);
            wB[tid] = expf(f);
            pidx[tid] = g_perm[b * NP + gp];
        } else {
            wS[tid] = 0.f; wB[tid] = 0.f; pidx[tid] = 0;
        }
    }
    __syncthreads();
    for (int x = tid; x < TILE * 16; x += 256) {
        int r = x >> 4, q = x & 15;
        reinterpret_cast<float4*>(hs[r])[q] =
            reinterpret_cast<const float4*>(g_h + (size_t)(b * NN + pidx[r]) * OCC)[q];
    }
    __syncthreads();

    int c = tid & 63, seg = tid >> 6;
    int rbeg = seg * SEG;

    {
        float aS = 0.f, aB = 0.f;
#pragma unroll 4
        for (int r = 0; r < SEG; r++) {
            int gr = rbeg + r;
            float hv = hs[gr][c];
            aS = fmaf(wS[gr], hv, aS);
            aB = fmaf(wB[gr], hv, aB);
        }
        segsum[seg][c] = make_float2(aS, aB);
    }
    if (tid < 4) {
        int rb = tid * SEG;
        float zS = 0.f, zB = 0.f;
#pragma unroll 4
        for (int r = 0; r < SEG; r++) { zS += wS[rb + r]; zB += wB[rb + r]; }
        segsumZ[tid] = make_float2(zS, zB);
    }
    __syncthreads();

    if (tid < 64) {
        float aS = 0.f, aB = 0.f;
#pragma unroll
        for (int s = 0; s < 4; s++) {
            segoff[s][tid] = make_float2(aS, aB);
            float2 v = segsum[s][tid];
            aS += v.x; aB += v.y;
        }
        g_ts[(b * NT + t) * OCC + tid] = make_float2(aS, aB);
    } else if (tid == 64) {
        float zS = 0.f, zB = 0.f;
#pragma unroll
        for (int s = 0; s < 4; s++) {
            segoffZ[s] = make_float2(zS, zB);
            float2 v = segsumZ[s];
            zS += v.x; zB += v.y;
        }
        g_tsZ[b * NT + t] = make_float2(zS, zB);
    }
    __syncthreads();

    {
        float2 o = segoff[seg][c];
        float aS = o.x, aB = o.y;
#pragma unroll 4
        for (int r = 0; r < SEG; r++) {
            int gr = rbeg + r;
            g_pre[(size_t)(b * KP + r0 + gr) * OCC + c] = make_float2(aS, aB);
            float hv = hs[gr][c];
            aS = fmaf(wS[gr], hv, aS);
            aB = fmaf(wB[gr], hv, aB);
        }
    }
    if (tid < 4) {
        int rb = tid * SEG;
        float2 o = segoffZ[tid];
        float zS = o.x, zB = o.y;
#pragma unroll 4
        for (int r = 0; r < SEG; r++) {
            g_preZ[b * KP + r0 + rb + r] = make_float2(zS, zB);
            zS += wS[rb + r]; zB += wB[rb + r];
        }
    }
}

// ---------------- kernel E: search + combine + relu + transpose (40 rows / block) ----------------
// grid (50, 16), block (64, 8) = 512
__global__ void __launch_bounds__(512, 2) k_out(float* __restrict__ out) {
    __shared__ float  fs[NN];
    __shared__ float  sm[40][OCC + 1];
    __shared__ float2 tstage[NT][OCC];
    __shared__ float2 to[NT + 1][OCC];
    __shared__ float2 ztstage[NT];
    __shared__ float  zpreS[NT + 1], zpreB[NT + 1];
    __shared__ int    kks[40];
    __shared__ float  f1s[40];
    __shared__ float4 rinfo[40];

    int b = blockIdx.y;
    int i0 = blockIdx.x * 40;
    int c = threadIdx.x, il = threadIdx.y;
    int tid = il * 64 + c;

    for (int x = tid; x < NN; x += 512)
        fs[x] = g_f2s[b * NP + x];
    {
        int ta = tid >> 6, ca = tid & 63;
        tstage[ta][ca] = g_ts[(b * NT + ta) * OCC + ca];
        int t2 = tid + 512;
        int tb = t2 >> 6, cb = t2 & 63;
        tstage[tb][cb] = g_ts[(b * NT + tb) * OCC + cb];
    }
    if (tid < NT) ztstage[tid] = g_tsZ[b * NT + tid];
    if (tid < 40) f1s[tid] = g_f1[b * NN + i0 + tid];
    __syncthreads();

    if (tid < 64) {
        float aS = 0.f, aB = 0.f;
#pragma unroll
        for (int t2 = 0; t2 < NT; t2++) {
            to[t2][tid] = make_float2(aS, aB);
            float2 v = tstage[t2][tid];
            aS += v.x; aB += v.y;
        }
        to[NT][tid] = make_float2(aS, aB);
    } else if (tid == 64) {
        float aS = 0.f, aB = 0.f;
#pragma unroll
        for (int t2 = 0; t2 < NT; t2++) {
            zpreS[t2] = aS; zpreB[t2] = aB;
            float2 z = ztstage[t2];
            aS += z.x; aB += z.y;
        }
        zpreS[NT] = aS; zpreB[NT] = aB;
    }
    __syncthreads();

    if (tid < 40) {
        float f1v = f1s[tid];
        float th = -f1v;
        int lo = 0, hi = NN;
        while (lo < hi) {
            int mid = (lo + hi) >> 1;
            if (fs[mid] < th) lo = mid + 1; else hi = mid;
        }
        int k = lo, t = lo >> 7;
        float2 preZ = g_preZ[b * KP + k];
        float pZS = zpreS[t] + preZ.x;
        float pZB = zpreB[t] + preZ.y;
        float A  = expf(f1v);
        float aa = expf(0.01f * f1v);
        float den = A * (zpreB[NT] - pZB) + aa * pZS;
        kks[tid] = k;
        rinfo[tid] = make_float4(A, aa, 1.f / den, 0.f);
    }
    __syncthreads();

    {
        float totB = to[NT][c].y;
        int kk[5];
#pragma unroll
        for (int g = 0; g < 5; g++) kk[g] = kks[g * 8 + il];
        float2 pv[5];
#pragma unroll
        for (int g = 0; g < 5; g++)
            pv[g] = g_pre[(size_t)(b * KP + kk[g]) * OCC + c];
#pragma unroll
        for (int g = 0; g < 5; g++) {
            int rl = g * 8 + il;
            float4 ri = rinfo[rl];
            float2 tov = to[kk[g] >> 7][c];
            float pS = tov.x + pv[g].x;
            float pB = tov.y + pv[g].y;
            float num = ri.x * (totB - pB) + ri.y * pS;
            sm[rl][c] = fmaxf(num * ri.z, 0.f);
        }
    }
    __syncthreads();

    {
        int c2 = tid / 40, i2 = tid % 40;
#pragma unroll
        for (int g = 0; g < 5; g++) {
            out[(b * OCC + c2) * NN + i0 + i2] = sm[i2][c2];
            i2 += 32; c2 += 12;
            if (i2 >= 40) { i2 -= 40; c2 += 1; }
        }
    }
}

// ---------------- launch ----------------
extern "C" void kernel_launch(void* const* d_in, const int* in_sizes, int n_in,
                              void* d_out, int out_size) {
    const float* inp = (const float*)d_in[0];   // (16, 64, 2000)
    const float* W   = (const float*)d_in[1];   // (64, 64)
    const float* a   = (const float*)d_in[2];   // (128, 1)
    // d_in[3] = GL : unused (softmax output strictly positive -> adjacency mask is a no-op)
    float* out = (float*)d_out;                 // (16, 64, 2000)

    k_h   <<<dim3(25, BB), 128>>>(inp, W, a);
    k_sort<<<BB, 1024>>>();
    k_tile<<<dim3(NT, BB), 256>>>();
    k_out <<<dim3(50, BB), dim3(64, 8)>>>(out);
}

// round 11
// speedup vs baseline: 1.2904x; 1.0025x over previous
#include <cuda_runtime.h>
#include <math.h>

#define BB 16
#define CC 64
#define NN 2000
#define OCC 64
#define NP 2048   // padded size for bitonic sort
#define TILE 128
#define NT 16     // NT*TILE = 2048 >= NN
#define KP 2048   // prefix index space

typedef unsigned long long u64;
typedef unsigned int u32;

// ---------------- scratch (no allocations allowed) ----------------
__device__ float  g_h[BB * NN * OCC];    // h[b][n][c]
__device__ float  g_f1[BB * NN];
__device__ float  g_f2[BB * NN];
__device__ float  g_f2s[BB * NP];        // sorted f2 (ascending)
__device__ int    g_perm[BB * NP];       // sorted rank -> original j
__device__ int    g_kk[BB * NN];         // per-row cutpoint (lower_bound of -f1 in sorted f2)
__device__ float2 g_pre[BB * KP * OCC];  // within-tile excl prefix {S=exp(.01 f2)*h, B=exp(f2)*h}
__device__ float2 g_preZ[BB * KP];       // within-tile excl prefix of weights {S,B}
__device__ float2 g_ts[BB * NT * OCC];   // per-tile sums {S,B}
__device__ float2 g_tsZ[BB * NT];        // per-tile weight sums {S,B}

__device__ __forceinline__ u32 fmap(float f) {   // monotone float->u32
    u32 u = __float_as_uint(f);
    return (u & 0x80000000u) ? ~u : (u | 0x80000000u);
}

// ---------------- kernel A: h = x^T W ; f1 = x^T (W a1), f2 = x^T (W a2) ----------------
// grid (25, 16), block 128; 80 n-columns per block; 5n x 8c register tile per thread
__global__ void k_h(const float* __restrict__ inp, const float* __restrict__ W,
                    const float* __restrict__ a) {
    __shared__ float xs[80][CC + 1];     // [nl][k]
    __shared__ float Ws[CC][OCC + 1];    // [k][c]
    __shared__ float as_[128];
    __shared__ float wa1[CC], wa2[CC];
    int b = blockIdx.y;
    int n0 = blockIdx.x * 80;
    int tid = threadIdx.x;               // 0..127

    for (int t = tid; t < CC * OCC; t += 128)
        Ws[t >> 6][t & 63] = W[t];
    for (int t = tid; t < 80 * CC; t += 128) {
        int c = t / 80, nl = t % 80;
        xs[nl][c] = inp[(b * CC + c) * NN + n0 + nl];
    }
    as_[tid] = a[tid];
    __syncthreads();

    {   // wa1 = W @ a1, wa2 = W @ a2
        int c = tid & 63;
        const float* av = as_ + (tid >> 6) * 64;
        float s = 0.f;
#pragma unroll
        for (int oc = 0; oc < 64; oc++)
            s = fmaf(Ws[c][oc], av[oc], s);
        if (tid < 64) wa1[c] = s; else wa2[c] = s;
    }

    // ---- register-tiled GEMM: thread owns rows nl0..nl0+4, cols c0..c0+7 ----
    {
        int cg = tid & 7, ng = tid >> 3;
        int c0 = cg * 8, nl0 = ng * 5;
        float4 accA[5], accB[5];
#pragma unroll
        for (int r = 0; r < 5; r++) {
            accA[r] = make_float4(0.f, 0.f, 0.f, 0.f);
            accB[r] = make_float4(0.f, 0.f, 0.f, 0.f);
        }
#pragma unroll 4
        for (int k = 0; k < CC; k++) {
            float w0 = Ws[k][c0],     w1 = Ws[k][c0 + 1], w2 = Ws[k][c0 + 2], w3 = Ws[k][c0 + 3];
            float w4 = Ws[k][c0 + 4], w5 = Ws[k][c0 + 5], w6 = Ws[k][c0 + 6], w7 = Ws[k][c0 + 7];
#pragma unroll
            for (int r = 0; r < 5; r++) {
                float xv = xs[nl0 + r][k];
                accA[r].x = fmaf(xv, w0, accA[r].x); accA[r].y = fmaf(xv, w1, accA[r].y);
                accA[r].z = fmaf(xv, w2, accA[r].z); accA[r].w = fmaf(xv, w3, accA[r].w);
                accB[r].x = fmaf(xv, w4, accB[r].x); accB[r].y = fmaf(xv, w5, accB[r].y);
                accB[r].z = fmaf(xv, w6, accB[r].z); accB[r].w = fmaf(xv, w7, accB[r].w);
            }
        }
#pragma unroll
        for (int r = 0; r < 5; r++) {
            float4* hrow = (float4*)(g_h + (size_t)(b * NN + n0 + nl0 + r) * OCC + c0);
            hrow[0] = accA[r];
            hrow[1] = accB[r];
        }
    }
    __syncthreads();

    if (tid < 80) {   // f1/f2 dot products
        float s1 = 0.f, s2 = 0.f;
#pragma unroll
        for (int k = 0; k < CC; k++) {
            float xv = xs[tid][k];
            s1 = fmaf(xv, wa1[k], s1);
            s2 = fmaf(xv, wa2[k], s2);
        }
        g_f1[b * NN + n0 + tid] = s1;
        g_f2[b * NN + n0 + tid] = s2;
    }
}

// ---------------- kernel C: per-batch bitonic sort (register + shfl hybrid) + search ----------------
__device__ __forceinline__ void reg_stage(u64& v0, u64& v1, int tid, int k, int jhi) {
    bool up = (((2 * tid) & k) == 0);
#pragma unroll
    for (int j = 32; j >= 2; j >>= 1) {
        if (j > jhi) continue;
        int h = j >> 1;
        u64 p0 = __shfl_xor_sync(0xffffffffu, v0, h);
        u64 p1 = __shfl_xor_sync(0xffffffffu, v1, h);
        bool takeMin = (((tid & h) == 0) == up);
        u64 lo0 = v0 < p0 ? v0 : p0, hi0 = v0 < p0 ? p0 : v0;
        u64 lo1 = v1 < p1 ? v1 : p1, hi1 = v1 < p1 ? p1 : v1;
        v0 = takeMin ? lo0 : hi0;
        v1 = takeMin ? lo1 : hi1;
    }
    if ((v0 > v1) == up) { u64 t = v0; v0 = v1; v1 = t; }
}

__global__ void k_sort() {
    __shared__ u64 s[NP];                 // 16 KB
    int b = blockIdx.x, tid = threadIdx.x;   // 1024 threads

    u64 v0, v1;
    {
        int i0 = 2 * tid, i1 = 2 * tid + 1;
        v0 = (i0 < NN) ? (((u64)fmap(g_f2[b * NN + i0]) << 32) | (u32)i0) : ~0ull;
        v1 = (i1 < NN) ? (((u64)fmap(g_f2[b * NN + i1]) << 32) | (u32)i1) : ~0ull;
    }

#pragma unroll
    for (int k = 2; k <= 64; k <<= 1)
        reg_stage(v0, v1, tid, k, k >> 1);

    s[2 * tid] = v0; s[2 * tid + 1] = v1;
    __syncthreads();

    for (int k = 128; k <= 2048; k <<= 1) {
        for (int j = k >> 1; j >= 64; j >>= 1) {
#pragma unroll
            for (int half = 0; half < 2; half++) {
                int i = tid + half * 1024;
                int ixj = i ^ j;
                if (ixj > i) {
                    bool up = ((i & k) == 0);
                    u64 a = s[i], x = s[ixj];
                    if (up ? (a > x) : (a < x)) { s[i] = x; s[ixj] = a; }
                }
            }
            __syncthreads();
        }
        v0 = s[2 * tid]; v1 = s[2 * tid + 1];
        reg_stage(v0, v1, tid, k, 32);
        s[2 * tid] = v0; s[2 * tid + 1] = v1;
        __syncthreads();
    }

    // unpack + write sorted keys/perm
#pragma unroll
    for (int half = 0; half < 2; half++) {
        int i = tid + half * 1024;
        u64 v = s[i];
        u32 hi = (u32)(v >> 32);
        hi = (hi & 0x80000000u) ? (hi ^ 0x80000000u) : ~hi;
        g_f2s[b * NP + i] = __uint_as_float(hi);
        g_perm[b * NP + i] = (int)(v & 0xffffffffu);
    }

    // per-row lower_bound of -f1 over the sorted smem keys (amortized once per batch)
    for (int i = tid; i < NN; i += 1024) {
        float th = -g_f1[b * NN + i];
        u64 thp = (u64)fmap(th) << 32;
        int lo = 0, hi = NN;
        while (lo < hi) {
            int mid = (lo + hi) >> 1;
            if (s[mid] < thp) lo = mid + 1; else hi = mid;
        }
        g_kk[b * NN + i] = lo;
    }
}

// ---------------- kernel D: within-tile exclusive prefixes + tile sums ----------------
// grid (NT, BB), block 256: 4 segments of 32 rows x 64 channels
#define SEG 32
__global__ void k_tile() {
    __shared__ float  hs[TILE][OCC];
    __shared__ float  wS[TILE], wB[TILE];
    __shared__ int    pidx[TILE];
    __shared__ float2 segsum[4][OCC];
    __shared__ float2 segoff[4][OCC];
    __shared__ float2 segsumZ[4], segoffZ[4];
    int b = blockIdx.y, t = blockIdx.x, tid = threadIdx.x;
    int r0 = t * TILE;

    if (tid < TILE) {
        int gp = r0 + tid;
        if (gp < NN) {
            float f = g_f2s[b * NP + gp];
            wS[tid] = expf(0.01f * f);
            wB[tid] = expf(f);
            pidx[tid] = g_perm[b * NP + gp];
        } else {
            wS[tid] = 0.f; wB[tid] = 0.f; pidx[tid] = 0;
        }
    }
    __syncthreads();
    for (int x = tid; x < TILE * 16; x += 256) {
        int r = x >> 4, q = x & 15;
        reinterpret_cast<float4*>(hs[r])[q] =
            reinterpret_cast<const float4*>(g_h + (size_t)(b * NN + pidx[r]) * OCC)[q];
    }
    __syncthreads();

    int c = tid & 63, seg = tid >> 6;
    int rbeg = seg * SEG;

    {
        float aS = 0.f, aB = 0.f;
#pragma unroll 4
        for (int r = 0; r < SEG; r++) {
            int gr = rbeg + r;
            float hv = hs[gr][c];
            aS = fmaf(wS[gr], hv, aS);
            aB = fmaf(wB[gr], hv, aB);
        }
        segsum[seg][c] = make_float2(aS, aB);
    }
    if (tid < 4) {
        int rb = tid * SEG;
        float zS = 0.f, zB = 0.f;
#pragma unroll 4
        for (int r = 0; r < SEG; r++) { zS += wS[rb + r]; zB += wB[rb + r]; }
        segsumZ[tid] = make_float2(zS, zB);
    }
    __syncthreads();

    if (tid < 64) {
        float aS = 0.f, aB = 0.f;
#pragma unroll
        for (int s = 0; s < 4; s++) {
            segoff[s][tid] = make_float2(aS, aB);
            float2 v = segsum[s][tid];
            aS += v.x; aB += v.y;
        }
        g_ts[(b * NT + t) * OCC + tid] = make_float2(aS, aB);
    } else if (tid == 64) {
        float zS = 0.f, zB = 0.f;
#pragma unroll
        for (int s = 0; s < 4; s++) {
            segoffZ[s] = make_float2(zS, zB);
            float2 v = segsumZ[s];
            zS += v.x; zB += v.y;
        }
        g_tsZ[b * NT + t] = make_float2(zS, zB);
    }
    __syncthreads();

    {
        float2 o = segoff[seg][c];
        float aS = o.x, aB = o.y;
#pragma unroll 4
        for (int r = 0; r < SEG; r++) {
            int gr = rbeg + r;
            g_pre[(size_t)(b * KP + r0 + gr) * OCC + c] = make_float2(aS, aB);
            float hv = hs[gr][c];
            aS = fmaf(wS[gr], hv, aS);
            aB = fmaf(wB[gr], hv, aB);
        }
    }
    if (tid < 4) {
        int rb = tid * SEG;
        float2 o = segoffZ[tid];
        float zS = o.x, zB = o.y;
#pragma unroll 4
        for (int r = 0; r < SEG; r++) {
            g_preZ[b * KP + r0 + rb + r] = make_float2(zS, zB);
            zS += wS[rb + r]; zB += wB[rb + r];
        }
    }
}

// ---------------- kernel E: combine + relu + transpose (40 rows / block) ----------------
// grid (50, 16), block (64, 8) = 512; no search, no fs staging
__global__ void __launch_bounds__(512, 2) k_out(float* __restrict__ out) {
    __shared__ float  sm[40][OCC + 1];
    __shared__ float2 tstage[NT][OCC];
    __shared__ float2 to[NT + 1][OCC];
    __shared__ float2 ztstage[NT];
    __shared__ int    kks[40];
    __shared__ float4 rinfo[40];          // {A, aa, rden, pad}

    int b = blockIdx.y;
    int i0 = blockIdx.x * 40;
    int c = threadIdx.x, il = threadIdx.y;
    int tid = il * 64 + c;

    // ---- phase 1: parallel staging + row-thread loads (threads 64..103 own rows) ----
    int rk = 0; float rA = 0.f, raa = 0.f; float2 rpreZ = make_float2(0.f, 0.f);
    {
        int ta = tid >> 6, ca = tid & 63;
        tstage[ta][ca] = g_ts[(b * NT + ta) * OCC + ca];
        int t2 = tid + 512;
        int tb = t2 >> 6, cb = t2 & 63;
        tstage[tb][cb] = g_ts[(b * NT + tb) * OCC + cb];
    }
    if (tid < NT) ztstage[tid] = g_tsZ[b * NT + tid];
    if (tid >= 64 && tid < 104) {
        int r = tid - 64;
        rk = g_kk[b * NN + i0 + r];
        float f1v = g_f1[b * NN + i0 + r];
        rpreZ = g_preZ[b * KP + rk];
        rA  = expf(f1v);
        raa = expf(0.01f * f1v);
        kks[r] = rk;
    }
    __syncthreads();

    // ---- phase 2: channel to-prefix (tid<64) || per-row Z-prefix + rinfo (tid 64..103) ----
    if (tid < 64) {
        float aS = 0.f, aB = 0.f;
#pragma unroll
        for (int t2 = 0; t2 < NT; t2++) {
            to[t2][tid] = make_float2(aS, aB);
            float2 v = tstage[t2][tid];
            aS += v.x; aB += v.y;
        }
        to[NT][tid] = make_float2(aS, aB);
    } else if (tid < 104) {
        int r = tid - 64;
        int t = rk >> 7;
        float pZS = rpreZ.x, pZB = rpreZ.y, totZB = 0.f;
#pragma unroll
        for (int t2 = 0; t2 < NT; t2++) {
            float2 z = ztstage[t2];
            if (t2 < t) { pZS += z.x; pZB += z.y; }
            totZB += z.y;
        }
        float den = rA * (totZB - pZB) + raa * pZS;
        rinfo[r] = make_float4(rA, raa, 1.f / den, 0.f);
    }
    __syncthreads();

    // ---- phase 3: combine (prefetch 5 g_pre loads, MLP=5) ----
    {
        float totB = to[NT][c].y;
        int kk[5];
#pragma unroll
        for (int g = 0; g < 5; g++) kk[g] = kks[g * 8 + il];
        float2 pv[5];
#pragma unroll
        for (int g = 0; g < 5; g++)
            pv[g] = g_pre[(size_t)(b * KP + kk[g]) * OCC + c];
#pragma unroll
        for (int g = 0; g < 5; g++) {
            int rl = g * 8 + il;
            float4 ri = rinfo[rl];
            float2 tov = to[kk[g] >> 7][c];
            float pS = tov.x + pv[g].x;
            float pB = tov.y + pv[g].y;
            float num = ri.x * (totB - pB) + ri.y * pS;
            sm[rl][c] = fmaxf(num * ri.z, 0.f);
        }
    }
    __syncthreads();

    // ---- phase 4: transpose-store ----
    {
        int c2 = tid / 40, i2 = tid % 40;
#pragma unroll
        for (int g = 0; g < 5; g++) {
            out[(b * OCC + c2) * NN + i0 + i2] = sm[i2][c2];
            i2 += 32; c2 += 12;            // +512 = +12*40 + 32
            if (i2 >= 40) { i2 -= 40; c2 += 1; }
        }
    }
}

// ---------------- launch ----------------
extern "C" void kernel_launch(void* const* d_in, const int* in_sizes, int n_in,
                              void* d_out, int out_size) {
    const float* inp = (const float*)d_in[0];   // (16, 64, 2000)
    const float* W   = (const float*)d_in[1];   // (64, 64)
    const float* a   = (const float*)d_in[2];   // (128, 1)
    // d_in[3] = GL : unused (softmax output strictly positive -> adjacency mask is a no-op)
    float* out = (float*)d_out;                 // (16, 64, 2000)

    k_h   <<<dim3(25, BB), 128>>>(inp, W, a);
    k_sort<<<BB, 1024>>>();
    k_tile<<<dim3(NT, BB), 256>>>();
    k_out <<<dim3(50, BB), dim3(64, 8)>>>(out);
}

// round 12
// speedup vs baseline: 1.3398x; 1.0383x over previous
#include <cuda_runtime.h>
#include <math.h>

#define BB 16
#define CC 64
#define NN 2000
#define OCC 64
#define NP 2048   // padded size for bitonic sort
#define TILE 128
#define NT 16     // NT*TILE = 2048 >= NN
#define KP 2048   // prefix index space

typedef unsigned long long u64;
typedef unsigned int u32;

// ---------------- scratch (no allocations allowed) ----------------
__device__ float  g_h[BB * NN * OCC];    // h[b][n][c]
__device__ float  g_f1[BB * NN];
__device__ float  g_f2[BB * NN];
__device__ float  g_f2s[BB * NP];        // sorted f2 (ascending)
__device__ int    g_perm[BB * NP];       // sorted rank -> original j
__device__ int    g_kk[BB * NN];         // per-row cutpoint (lower_bound of -f1 in sorted f2)
__device__ float2 g_pre[BB * KP * OCC];  // within-tile excl prefix {S=exp(.01 f2)*h, B=exp(f2)*h}
__device__ float2 g_preZ[BB * KP];       // within-tile excl prefix of weights {S,B}
__device__ float2 g_ts[BB * NT * OCC];   // per-tile sums {S,B}
__device__ float2 g_tsZ[BB * NT];        // per-tile weight sums {S,B}

__device__ __forceinline__ u32 fmap(float f) {   // monotone float->u32
    u32 u = __float_as_uint(f);
    return (u & 0x80000000u) ? ~u : (u | 0x80000000u);
}

// ---------------- kernel A: h = x^T W ; f1 = x^T (W a1), f2 = x^T (W a2) ----------------
// grid (25, 16), block 128; 80 n-columns per block; 5n x 8c register tile per thread
__global__ void k_h(const float* __restrict__ inp, const float* __restrict__ W,
                    const float* __restrict__ a) {
    __shared__ float xs[80][CC + 1];     // [nl][k]
    __shared__ float Ws[CC][OCC + 1];    // [k][c]
    __shared__ float as_[128];
    __shared__ float wa1[CC], wa2[CC];
    int b = blockIdx.y;
    int n0 = blockIdx.x * 80;
    int tid = threadIdx.x;               // 0..127

    for (int t = tid; t < CC * OCC; t += 128)
        Ws[t >> 6][t & 63] = W[t];
    for (int t = tid; t < 80 * CC; t += 128) {
        int c = t / 80, nl = t % 80;
        xs[nl][c] = inp[(b * CC + c) * NN + n0 + nl];
    }
    as_[tid] = a[tid];
    __syncthreads();

    {   // wa1 = W @ a1, wa2 = W @ a2
        int c = tid & 63;
        const float* av = as_ + (tid >> 6) * 64;
        float s = 0.f;
#pragma unroll
        for (int oc = 0; oc < 64; oc++)
            s = fmaf(Ws[c][oc], av[oc], s);
        if (tid < 64) wa1[c] = s; else wa2[c] = s;
    }

    // ---- register-tiled GEMM: thread owns rows nl0..nl0+4, cols c0..c0+7 ----
    {
        int cg = tid & 7, ng = tid >> 3;
        int c0 = cg * 8, nl0 = ng * 5;
        float4 accA[5], accB[5];
#pragma unroll
        for (int r = 0; r < 5; r++) {
            accA[r] = make_float4(0.f, 0.f, 0.f, 0.f);
            accB[r] = make_float4(0.f, 0.f, 0.f, 0.f);
        }
#pragma unroll 4
        for (int k = 0; k < CC; k++) {
            float w0 = Ws[k][c0],     w1 = Ws[k][c0 + 1], w2 = Ws[k][c0 + 2], w3 = Ws[k][c0 + 3];
            float w4 = Ws[k][c0 + 4], w5 = Ws[k][c0 + 5], w6 = Ws[k][c0 + 6], w7 = Ws[k][c0 + 7];
#pragma unroll
            for (int r = 0; r < 5; r++) {
                float xv = xs[nl0 + r][k];
                accA[r].x = fmaf(xv, w0, accA[r].x); accA[r].y = fmaf(xv, w1, accA[r].y);
                accA[r].z = fmaf(xv, w2, accA[r].z); accA[r].w = fmaf(xv, w3, accA[r].w);
                accB[r].x = fmaf(xv, w4, accB[r].x); accB[r].y = fmaf(xv, w5, accB[r].y);
                accB[r].z = fmaf(xv, w6, accB[r].z); accB[r].w = fmaf(xv, w7, accB[r].w);
            }
        }
#pragma unroll
        for (int r = 0; r < 5; r++) {
            float4* hrow = (float4*)(g_h + (size_t)(b * NN + n0 + nl0 + r) * OCC + c0);
            hrow[0] = accA[r];
            hrow[1] = accB[r];
        }
    }
    __syncthreads();

    if (tid < 80) {   // f1/f2 dot products
        float s1 = 0.f, s2 = 0.f;
#pragma unroll
        for (int k = 0; k < CC; k++) {
            float xv = xs[tid][k];
            s1 = fmaf(xv, wa1[k], s1);
            s2 = fmaf(xv, wa2[k], s2);
        }
        g_f1[b * NN + n0 + tid] = s1;
        g_f2[b * NN + n0 + tid] = s2;
    }
}

// ---------------- kernel C: per-batch bitonic sort (register + shfl hybrid) + search ----------------
__device__ __forceinline__ void reg_stage(u64& v0, u64& v1, int tid, int k, int jhi) {
    bool up = (((2 * tid) & k) == 0);
#pragma unroll
    for (int j = 32; j >= 2; j >>= 1) {
        if (j > jhi) continue;
        int h = j >> 1;
        u64 p0 = __shfl_xor_sync(0xffffffffu, v0, h);
        u64 p1 = __shfl_xor_sync(0xffffffffu, v1, h);
        bool takeMin = (((tid & h) == 0) == up);
        u64 lo0 = v0 < p0 ? v0 : p0, hi0 = v0 < p0 ? p0 : v0;
        u64 lo1 = v1 < p1 ? v1 : p1, hi1 = v1 < p1 ? p1 : v1;
        v0 = takeMin ? lo0 : hi0;
        v1 = takeMin ? lo1 : hi1;
    }
    if ((v0 > v1) == up) { u64 t = v0; v0 = v1; v1 = t; }
}

__global__ void k_sort() {
    __shared__ u64 s[NP];                 // 16 KB
    int b = blockIdx.x, tid = threadIdx.x;   // 1024 threads

    u64 v0, v1;
    {
        int i0 = 2 * tid, i1 = 2 * tid + 1;
        v0 = (i0 < NN) ? (((u64)fmap(g_f2[b * NN + i0]) << 32) | (u32)i0) : ~0ull;
        v1 = (i1 < NN) ? (((u64)fmap(g_f2[b * NN + i1]) << 32) | (u32)i1) : ~0ull;
    }

#pragma unroll
    for (int k = 2; k <= 64; k <<= 1)
        reg_stage(v0, v1, tid, k, k >> 1);

    s[2 * tid] = v0; s[2 * tid + 1] = v1;
    __syncthreads();

    for (int k = 128; k <= 2048; k <<= 1) {
        for (int j = k >> 1; j >= 64; j >>= 1) {
#pragma unroll
            for (int half = 0; half < 2; half++) {
                int i = tid + half * 1024;
                int ixj = i ^ j;
                if (ixj > i) {
                    bool up = ((i & k) == 0);
                    u64 a = s[i], x = s[ixj];
                    if (up ? (a > x) : (a < x)) { s[i] = x; s[ixj] = a; }
                }
            }
            __syncthreads();
        }
        v0 = s[2 * tid]; v1 = s[2 * tid + 1];
        reg_stage(v0, v1, tid, k, 32);
        s[2 * tid] = v0; s[2 * tid + 1] = v1;
        __syncthreads();
    }

    // unpack + write sorted keys/perm
#pragma unroll
    for (int half = 0; half < 2; half++) {
        int i = tid + half * 1024;
        u64 v = s[i];
        u32 hi = (u32)(v >> 32);
        hi = (hi & 0x80000000u) ? (hi ^ 0x80000000u) : ~hi;
        g_f2s[b * NP + i] = __uint_as_float(hi);
        g_perm[b * NP + i] = (int)(v & 0xffffffffu);
    }

    // per-row lower_bound of -f1 over the sorted smem keys
    for (int i = tid; i < NN; i += 1024) {
        float th = -g_f1[b * NN + i];
        u64 thp = (u64)fmap(th) << 32;
        int lo = 0, hi = NN;
        while (lo < hi) {
            int mid = (lo + hi) >> 1;
            if (s[mid] < thp) lo = mid + 1; else hi = mid;
        }
        g_kk[b * NN + i] = lo;
    }
}

// ---------------- kernel D: within-tile exclusive prefixes + tile sums ----------------
// grid (NT, BB), block 256: 4 segments of 32 rows x 64 channels
#define SEG 32
__global__ void k_tile() {
    __shared__ float  hs[TILE][OCC];
    __shared__ float  wS[TILE], wB[TILE];
    __shared__ int    pidx[TILE];
    __shared__ float2 segsum[4][OCC];
    __shared__ float2 segoff[4][OCC];
    __shared__ float2 segsumZ[4], segoffZ[4];
    int b = blockIdx.y, t = blockIdx.x, tid = threadIdx.x;
    int r0 = t * TILE;

    if (tid < TILE) {
        int gp = r0 + tid;
        if (gp < NN) {
            float f = g_f2s[b * NP + gp];
            wS[tid] = expf(0.01f * f);
            wB[tid] = expf(f);
            pidx[tid] = g_perm[b * NP + gp];
        } else {
            wS[tid] = 0.f; wB[tid] = 0.f; pidx[tid] = 0;
        }
    }
    __syncthreads();
    for (int x = tid; x < TILE * 16; x += 256) {
        int r = x >> 4, q = x & 15;
        reinterpret_cast<float4*>(hs[r])[q] =
            reinterpret_cast<const float4*>(g_h + (size_t)(b * NN + pidx[r]) * OCC)[q];
    }
    __syncthreads();

    int c = tid & 63, seg = tid >> 6;
    int rbeg = seg * SEG;

    {
        float aS = 0.f, aB = 0.f;
#pragma unroll 4
        for (int r = 0; r < SEG; r++) {
            int gr = rbeg + r;
            float hv = hs[gr][c];
            aS = fmaf(wS[gr], hv, aS);
            aB = fmaf(wB[gr], hv, aB);
        }
        segsum[seg][c] = make_float2(aS, aB);
    }
    if (tid < 4) {
        int rb = tid * SEG;
        float zS = 0.f, zB = 0.f;
#pragma unroll 4
        for (int r = 0; r < SEG; r++) { zS += wS[rb + r]; zB += wB[rb + r]; }
        segsumZ[tid] = make_float2(zS, zB);
    }
    __syncthreads();

    if (tid < 64) {
        float aS = 0.f, aB = 0.f;
#pragma unroll
        for (int s = 0; s < 4; s++) {
            segoff[s][tid] = make_float2(aS, aB);
            float2 v = segsum[s][tid];
            aS += v.x; aB += v.y;
        }
        g_ts[(b * NT + t) * OCC + tid] = make_float2(aS, aB);
    } else if (tid == 64) {
        float zS = 0.f, zB = 0.f;
#pragma unroll
        for (int s = 0; s < 4; s++) {
            segoffZ[s] = make_float2(zS, zB);
            float2 v = segsumZ[s];
            zS += v.x; zB += v.y;
        }
        g_tsZ[b * NT + t] = make_float2(zS, zB);
    }
    __syncthreads();

    {
        float2 o = segoff[seg][c];
        float aS = o.x, aB = o.y;
#pragma unroll 4
        for (int r = 0; r < SEG; r++) {
            int gr = rbeg + r;
            g_pre[(size_t)(b * KP + r0 + gr) * OCC + c] = make_float2(aS, aB);
            float hv = hs[gr][c];
            aS = fmaf(wS[gr], hv, aS);
            aB = fmaf(wB[gr], hv, aB);
        }
    }
    if (tid < 4) {
        int rb = tid * SEG;
        float2 o = segoffZ[tid];
        float zS = o.x, zB = o.y;
#pragma unroll 4
        for (int r = 0; r < SEG; r++) {
            g_preZ[b * KP + r0 + rb + r] = make_float2(zS, zB);
            zS += wS[rb + r]; zB += wB[rb + r];
        }
    }
}

// ---------------- kernel E: combine + relu + transpose, single-wave grid ----------------
// grid (18, 16), block 512; 112 rows per block (last block 96)
#define ROWS 112
__global__ void __launch_bounds__(512, 2) k_out(float* __restrict__ out) {
    __shared__ float  sm[ROWS][OCC + 1];  // 29.1 KB
    __shared__ float2 to[NT + 1][OCC];    // 8.7 KB: [0]=0, then tile sums -> in-place prefix
    __shared__ float2 zt[NT];             // raw Z tile sums
    __shared__ int    kks[ROWS];
    __shared__ float4 rinfo[ROWS];        // {A, aa, rden, pad}

    int b = blockIdx.y;
    int i0 = blockIdx.x * ROWS;
    int rows = min(ROWS, NN - i0);
    int tid = threadIdx.x;
    int c = tid & 63, il = tid >> 6;      // il 0..7

    // ---- phase 1: parallel staging ----
    {
        int ta = tid >> 6, ca = tid & 63;
        to[ta + 1][ca] = g_ts[(b * NT + ta) * OCC + ca];
        int t2 = tid + 512;
        int tb = t2 >> 6, cb = t2 & 63;
        to[tb + 1][cb] = g_ts[(b * NT + tb) * OCC + cb];
    }
    if (tid < 64) to[0][tid] = make_float2(0.f, 0.f);
    if (tid >= 448 && tid < 464) zt[tid - 448] = g_tsZ[b * NT + (tid - 448)];
    int rk = 0; float rf1 = 0.f; float2 rpreZ = make_float2(0.f, 0.f);
    if (tid >= 64 && tid < 64 + ROWS) {
        int r = tid - 64;
        if (r < rows) {
            rk  = g_kk[b * NN + i0 + r];
            rf1 = g_f1[b * NN + i0 + r];
            rpreZ = g_preZ[b * KP + rk];
            kks[r] = rk;
        }
    }
    __syncthreads();

    // ---- phase 2: channel to-prefix (tid<64) || per-row Z math (tid 64..64+ROWS) ----
    if (tid < 64) {
        // in-place: to[t] becomes exclusive offset for tile t; to[NT] = total
#pragma unroll
        for (int t2 = 1; t2 <= NT; t2++) {
            float2 p = to[t2 - 1][tid], v = to[t2][tid];
            to[t2][tid] = make_float2(p.x + v.x, p.y + v.y);
        }
        // after loop: to[t] = inclusive sum of tiles 0..t-1 shifted? verify:
        // initial: to[0]=0, to[t+1]=ts[t]. After t2 sweep: to[t2] = sum_{t'<t2} ts[t'] ✓
    } else if (tid < 64 + ROWS) {
        int r = tid - 64;
        if (r < rows) {
            int t = rk >> 7;
            float pZS = rpreZ.x, pZB = rpreZ.y, totZB = 0.f;
#pragma unroll
            for (int t2 = 0; t2 < NT; t2++) {
                float2 z = zt[t2];
                if (t2 < t) { pZS += z.x; pZB += z.y; }
                totZB += z.y;
            }
            float A  = expf(rf1);
            float aa = expf(0.01f * rf1);
            float den = A * (totZB - pZB) + aa * pZS;
            rinfo[r] = make_float4(A, aa, 1.f / den, 0.f);
        }
    }
    __syncthreads();

    // ---- phase 3: combine, 14 chunks of 8 rows; prefetch in batches of 7 ----
    {
        float totB = to[NT][c].y;
#pragma unroll
        for (int half = 0; half < 2; half++) {
            int kk[7]; float2 pv[7];
#pragma unroll
            for (int g = 0; g < 7; g++) {
                int rl = (half * 7 + g) * 8 + il;
                kk[g] = (rl < rows) ? kks[rl] : 0;
            }
#pragma unroll
            for (int g = 0; g < 7; g++)
                pv[g] = g_pre[(size_t)(b * KP + kk[g]) * OCC + c];
#pragma unroll
            for (int g = 0; g < 7; g++) {
                int rl = (half * 7 + g) * 8 + il;
                if (rl < rows) {
                    float4 ri = rinfo[rl];
                    float2 tov = to[kk[g] >> 7][c];
                    float pS = tov.x + pv[g].x;
                    float pB = tov.y + pv[g].y;
                    float num = ri.x * (totB - pB) + ri.y * pS;
                    sm[rl][c] = fmaxf(num * ri.z, 0.f);
                }
            }
        }
    }
    __syncthreads();

    // ---- phase 4: transpose-store (c2, i2) incremental; bounds for last block ----
    {
        int c2 = tid / ROWS, i2 = tid % ROWS;
#pragma unroll
        for (int g = 0; g < 14; g++) {
            if (i2 < rows)
                out[(b * OCC + c2) * NN + i0 + i2] = sm[i2][c2];
            i2 += 64; c2 += 4;             // +512 = +4*112 + 64
            if (i2 >= ROWS) { i2 -= ROWS; c2 += 1; }
        }
    }
}

// ---------------- launch ----------------
extern "C" void kernel_launch(void* const* d_in, const int* in_sizes, int n_in,
                              void* d_out, int out_size) {
    const float* inp = (const float*)d_in[0];   // (16, 64, 2000)
    const float* W   = (const float*)d_in[1];   // (64, 64)
    const float* a   = (const float*)d_in[2];   // (128, 1)
    // d_in[3] = GL : unused (softmax output strictly positive -> adjacency mask is a no-op)
    float* out = (float*)d_out;                 // (16, 64, 2000)

    k_h   <<<dim3(25, BB), 128>>>(inp, W, a);
    k_sort<<<BB, 1024>>>();
    k_tile<<<dim3(NT, BB), 256>>>();
    k_out <<<dim3(18, BB), 512>>>(out);
}

// round 13
// speedup vs baseline: 1.4611x; 1.0905x over previous
#include <cuda_runtime.h>
#include <math.h>

#define BB 16
#define CC 64
#define NN 2000
#define OCC 64
#define NP 2048   // padded size for bitonic sort
#define TILE 128
#define NT 16     // NT*TILE = 2048 >= NN
#define KP 2048   // prefix index space

typedef unsigned long long u64;
typedef unsigned int u32;

// ---------------- scratch (no allocations allowed) ----------------
__device__ float  g_h[BB * NN * OCC];    // h[b][n][c]
__device__ float  g_f1[BB * NN];
__device__ float  g_f2[BB * NN];
__device__ float  g_f2s[BB * NP];        // sorted f2 (ascending)
__device__ int    g_perm[BB * NP];       // sorted rank -> original j
__device__ int    g_kk[BB * NN];         // per-row cutpoint (lower_bound of -f1 in sorted f2)
__device__ float2 g_pre[BB * KP * OCC];  // within-tile excl prefix {S=exp(.01 f2)*h, B=exp(f2)*h}
__device__ float2 g_preZ[BB * KP];       // within-tile excl prefix of weights {S,B}
__device__ float2 g_ts[BB * NT * OCC];   // per-tile sums {S,B}
__device__ float2 g_tsZ[BB * NT];        // per-tile weight sums {S,B}

__device__ __forceinline__ u32 fmap(float f) {   // monotone float->u32
    u32 u = __float_as_uint(f);
    return (u & 0x80000000u) ? ~u : (u | 0x80000000u);
}

// ---------------- kernel F: f1 = x^T (W a1), f2 = x^T (W a2), straight from inp ----------------
// grid (8, 16), block 256; 250 rows per block
__global__ void k_f(const float* __restrict__ inp, const float* __restrict__ W,
                    const float* __restrict__ a) {
    __shared__ float as_[128];
    __shared__ float wa1[CC], wa2[CC];
    int b = blockIdx.y;
    int n0 = blockIdx.x * 250;
    int tid = threadIdx.x;

    if (tid < 128) as_[tid] = a[tid];
    __syncthreads();
    if (tid < 128) {   // wa1 = W @ a1, wa2 = W @ a2 (W reads are L2-hot)
        int c = tid & 63;
        const float* av = as_ + (tid >> 6) * 64;
        float s = 0.f;
#pragma unroll
        for (int oc = 0; oc < 64; oc++)
            s = fmaf(W[c * 64 + oc], av[oc], s);
        if (tid < 64) wa1[c] = s; else wa2[c] = s;
    }
    __syncthreads();

    if (tid < 250) {
        int n = n0 + tid;
        float s1 = 0.f, s2 = 0.f;
#pragma unroll 8
        for (int c = 0; c < CC; c++) {
            float xv = inp[(b * CC + c) * NN + n];   // coalesced across tid
            s1 = fmaf(xv, wa1[c], s1);
            s2 = fmaf(xv, wa2[c], s2);
        }
        g_f1[b * NN + n] = s1;
        g_f2[b * NN + n] = s2;
    }
}

// ---------------- kernel A: h = x^T W (pure GEMM) ----------------
// grid (25, 16), block 128; 80 n-columns per block; 5n x 8c register tile per thread
__global__ void k_h(const float* __restrict__ inp, const float* __restrict__ W) {
    __shared__ float xs[80][CC + 1];     // [nl][k]
    __shared__ float Ws[CC][OCC + 1];    // [k][c]
    int b = blockIdx.y;
    int n0 = blockIdx.x * 80;
    int tid = threadIdx.x;               // 0..127

    for (int t = tid; t < CC * OCC; t += 128)
        Ws[t >> 6][t & 63] = W[t];
    for (int t = tid; t < 80 * CC; t += 128) {
        int c = t / 80, nl = t % 80;
        xs[nl][c] = inp[(b * CC + c) * NN + n0 + nl];
    }
    __syncthreads();

    {
        int cg = tid & 7, ng = tid >> 3;
        int c0 = cg * 8, nl0 = ng * 5;
        float4 accA[5], accB[5];
#pragma unroll
        for (int r = 0; r < 5; r++) {
            accA[r] = make_float4(0.f, 0.f, 0.f, 0.f);
            accB[r] = make_float4(0.f, 0.f, 0.f, 0.f);
        }
#pragma unroll 4
        for (int k = 0; k < CC; k++) {
            float w0 = Ws[k][c0],     w1 = Ws[k][c0 + 1], w2 = Ws[k][c0 + 2], w3 = Ws[k][c0 + 3];
            float w4 = Ws[k][c0 + 4], w5 = Ws[k][c0 + 5], w6 = Ws[k][c0 + 6], w7 = Ws[k][c0 + 7];
#pragma unroll
            for (int r = 0; r < 5; r++) {
                float xv = xs[nl0 + r][k];
                accA[r].x = fmaf(xv, w0, accA[r].x); accA[r].y = fmaf(xv, w1, accA[r].y);
                accA[r].z = fmaf(xv, w2, accA[r].z); accA[r].w = fmaf(xv, w3, accA[r].w);
                accB[r].x = fmaf(xv, w4, accB[r].x); accB[r].y = fmaf(xv, w5, accB[r].y);
                accB[r].z = fmaf(xv, w6, accB[r].z); accB[r].w = fmaf(xv, w7, accB[r].w);
            }
        }
#pragma unroll
        for (int r = 0; r < 5; r++) {
            float4* hrow = (float4*)(g_h + (size_t)(b * NN + n0 + nl0 + r) * OCC + c0);
            hrow[0] = accA[r];
            hrow[1] = accB[r];
        }
    }
}

// ---------------- kernel C: per-batch bitonic sort (register + shfl hybrid) + search ----------------
__device__ __forceinline__ void reg_stage(u64& v0, u64& v1, int tid, int k, int jhi) {
    bool up = (((2 * tid) & k) == 0);
#pragma unroll
    for (int j = 32; j >= 2; j >>= 1) {
        if (j > jhi) continue;
        int h = j >> 1;
        u64 p0 = __shfl_xor_sync(0xffffffffu, v0, h);
        u64 p1 = __shfl_xor_sync(0xffffffffu, v1, h);
        bool takeMin = (((tid & h) == 0) == up);
        u64 lo0 = v0 < p0 ? v0 : p0, hi0 = v0 < p0 ? p0 : v0;
        u64 lo1 = v1 < p1 ? v1 : p1, hi1 = v1 < p1 ? p1 : v1;
        v0 = takeMin ? lo0 : hi0;
        v1 = takeMin ? lo1 : hi1;
    }
    if ((v0 > v1) == up) { u64 t = v0; v0 = v1; v1 = t; }
}

__global__ void k_sort() {
    __shared__ u64 s[NP];                 // 16 KB
    int b = blockIdx.x, tid = threadIdx.x;   // 1024 threads

    u64 v0, v1;
    {
        int i0 = 2 * tid, i1 = 2 * tid + 1;
        v0 = (i0 < NN) ? (((u64)fmap(g_f2[b * NN + i0]) << 32) | (u32)i0) : ~0ull;
        v1 = (i1 < NN) ? (((u64)fmap(g_f2[b * NN + i1]) << 32) | (u32)i1) : ~0ull;
    }

#pragma unroll
    for (int k = 2; k <= 64; k <<= 1)
        reg_stage(v0, v1, tid, k, k >> 1);

    s[2 * tid] = v0; s[2 * tid + 1] = v1;
    __syncthreads();

    for (int k = 128; k <= 2048; k <<= 1) {
        for (int j = k >> 1; j >= 64; j >>= 1) {
#pragma unroll
            for (int half = 0; half < 2; half++) {
                int i = tid + half * 1024;
                int ixj = i ^ j;
                if (ixj > i) {
                    bool up = ((i & k) == 0);
                    u64 a = s[i], x = s[ixj];
                    if (up ? (a > x) : (a < x)) { s[i] = x; s[ixj] = a; }
                }
            }
            __syncthreads();
        }
        v0 = s[2 * tid]; v1 = s[2 * tid + 1];
        reg_stage(v0, v1, tid, k, 32);
        s[2 * tid] = v0; s[2 * tid + 1] = v1;
        __syncthreads();
    }

    // unpack + write sorted keys/perm
#pragma unroll
    for (int half = 0; half < 2; half++) {
        int i = tid + half * 1024;
        u64 v = s[i];
        u32 hi = (u32)(v >> 32);
        hi = (hi & 0x80000000u) ? (hi ^ 0x80000000u) : ~hi;
        g_f2s[b * NP + i] = __uint_as_float(hi);
        g_perm[b * NP + i] = (int)(v & 0xffffffffu);
    }

    // per-row lower_bound of -f1 over the sorted smem keys
    for (int i = tid; i < NN; i += 1024) {
        float th = -g_f1[b * NN + i];
        u64 thp = (u64)fmap(th) << 32;
        int lo = 0, hi = NN;
        while (lo < hi) {
            int mid = (lo + hi) >> 1;
            if (s[mid] < thp) lo = mid + 1; else hi = mid;
        }
        g_kk[b * NN + i] = lo;
    }
}

// ---------------- kernel D: within-tile exclusive prefixes + tile sums ----------------
// grid (NT, BB), block 256: 4 segments of 32 rows x 64 channels
#define SEG 32
__global__ void k_tile() {
    __shared__ float  hs[TILE][OCC];
    __shared__ float  wS[TILE], wB[TILE];
    __shared__ int    pidx[TILE];
    __shared__ float2 segsum[4][OCC];
    __shared__ float2 segoff[4][OCC];
    __shared__ float2 segsumZ[4], segoffZ[4];
    int b = blockIdx.y, t = blockIdx.x, tid = threadIdx.x;
    int r0 = t * TILE;

    if (tid < TILE) {
        int gp = r0 + tid;
        if (gp < NN) {
            float f = g_f2s[b * NP + gp];
            wS[tid] = expf(0.01f * f);
            wB[tid] = expf(f);
            pidx[tid] = g_perm[b * NP + gp];
        } else {
            wS[tid] = 0.f; wB[tid] = 0.f; pidx[tid] = 0;
        }
    }
    __syncthreads();
    for (int x = tid; x < TILE * 16; x += 256) {
        int r = x >> 4, q = x & 15;
        reinterpret_cast<float4*>(hs[r])[q] =
            reinterpret_cast<const float4*>(g_h + (size_t)(b * NN + pidx[r]) * OCC)[q];
    }
    __syncthreads();

    int c = tid & 63, seg = tid >> 6;
    int rbeg = seg * SEG;

    {
        float aS = 0.f, aB = 0.f;
#pragma unroll 4
        for (int r = 0; r < SEG; r++) {
            int gr = rbeg + r;
            float hv = hs[gr][c];
            aS = fmaf(wS[gr], hv, aS);
            aB = fmaf(wB[gr], hv, aB);
        }
        segsum[seg][c] = make_float2(aS, aB);
    }
    if (tid < 4) {
        int rb = tid * SEG;
        float zS = 0.f, zB = 0.f;
#pragma unroll 4
        for (int r = 0; r < SEG; r++) { zS += wS[rb + r]; zB += wB[rb + r]; }
        segsumZ[tid] = make_float2(zS, zB);
    }
    __syncthreads();

    if (tid < 64) {
        float aS = 0.f, aB = 0.f;
#pragma unroll
        for (int s = 0; s < 4; s++) {
            segoff[s][tid] = make_float2(aS, aB);
            float2 v = segsum[s][tid];
            aS += v.x; aB += v.y;
        }
        g_ts[(b * NT + t) * OCC + tid] = make_float2(aS, aB);
    } else if (tid == 64) {
        float zS = 0.f, zB = 0.f;
#pragma unroll
        for (int s = 0; s < 4; s++) {
            segoffZ[s] = make_float2(zS, zB);
            float2 v = segsumZ[s];
            zS += v.x; zB += v.y;
        }
        g_tsZ[b * NT + t] = make_float2(zS, zB);
    }
    __syncthreads();

    {
        float2 o = segoff[seg][c];
        float aS = o.x, aB = o.y;
#pragma unroll 4
        for (int r = 0; r < SEG; r++) {
            int gr = rbeg + r;
            g_pre[(size_t)(b * KP + r0 + gr) * OCC + c] = make_float2(aS, aB);
            float hv = hs[gr][c];
            aS = fmaf(wS[gr], hv, aS);
            aB = fmaf(wB[gr], hv, aB);
        }
    }
    if (tid < 4) {
        int rb = tid * SEG;
        float2 o = segoffZ[tid];
        float zS = o.x, zB = o.y;
#pragma unroll 4
        for (int r = 0; r < SEG; r++) {
            g_preZ[b * KP + r0 + rb + r] = make_float2(zS, zB);
            zS += wS[rb + r]; zB += wB[rb + r];
        }
    }
}

// ---------------- kernel E: combine + relu + transpose, single-wave grid ----------------
// grid (18, 16), block 512; 112 rows per block (last block 96)
#define ROWS 112
__global__ void __launch_bounds__(512, 2) k_out(float* __restrict__ out) {
    __shared__ float  sm[ROWS][OCC + 1];
    __shared__ float2 to[NT + 1][OCC];
    __shared__ float2 zt[NT];
    __shared__ int    kks[ROWS];
    __shared__ float4 rinfo[ROWS];

    int b = blockIdx.y;
    int i0 = blockIdx.x * ROWS;
    int rows = min(ROWS, NN - i0);
    int tid = threadIdx.x;
    int c = tid & 63, il = tid >> 6;

    {
        int ta = tid >> 6, ca = tid & 63;
        to[ta + 1][ca] = g_ts[(b * NT + ta) * OCC + ca];
        int t2 = tid + 512;
        int tb = t2 >> 6, cb = t2 & 63;
        to[tb + 1][cb] = g_ts[(b * NT + tb) * OCC + cb];
    }
    if (tid < 64) to[0][tid] = make_float2(0.f, 0.f);
    if (tid >= 448 && tid < 464) zt[tid - 448] = g_tsZ[b * NT + (tid - 448)];
    int rk = 0; float rf1 = 0.f; float2 rpreZ = make_float2(0.f, 0.f);
    if (tid >= 64 && tid < 64 + ROWS) {
        int r = tid - 64;
        if (r < rows) {
            rk  = g_kk[b * NN + i0 + r];
            rf1 = g_f1[b * NN + i0 + r];
            rpreZ = g_preZ[b * KP + rk];
            kks[r] = rk;
        }
    }
    __syncthreads();

    if (tid < 64) {
#pragma unroll
        for (int t2 = 1; t2 <= NT; t2++) {
            float2 p = to[t2 - 1][tid], v = to[t2][tid];
            to[t2][tid] = make_float2(p.x + v.x, p.y + v.y);
        }
    } else if (tid < 64 + ROWS) {
        int r = tid - 64;
        if (r < rows) {
            int t = rk >> 7;
            float pZS = rpreZ.x, pZB = rpreZ.y, totZB = 0.f;
#pragma unroll
            for (int t2 = 0; t2 < NT; t2++) {
                float2 z = zt[t2];
                if (t2 < t) { pZS += z.x; pZB += z.y; }
                totZB += z.y;
            }
            float A  = expf(rf1);
            float aa = expf(0.01f * rf1);
            float den = A * (totZB - pZB) + aa * pZS;
            rinfo[r] = make_float4(A, aa, 1.f / den, 0.f);
        }
    }
    __syncthreads();

    {
        float totB = to[NT][c].y;
#pragma unroll
        for (int half = 0; half < 2; half++) {
            int kk[7]; float2 pv[7];
#pragma unroll
            for (int g = 0; g < 7; g++) {
                int rl = (half * 7 + g) * 8 + il;
                kk[g] = (rl < rows) ? kks[rl] : 0;
            }
#pragma unroll
            for (int g = 0; g < 7; g++)
                pv[g] = g_pre[(size_t)(b * KP + kk[g]) * OCC + c];
#pragma unroll
            for (int g = 0; g < 7; g++) {
                int rl = (half * 7 + g) * 8 + il;
                if (rl < rows) {
                    float4 ri = rinfo[rl];
                    float2 tov = to[kk[g] >> 7][c];
                    float pS = tov.x + pv[g].x;
                    float pB = tov.y + pv[g].y;
                    float num = ri.x * (totB - pB) + ri.y * pS;
                    sm[rl][c] = fmaxf(num * ri.z, 0.f);
                }
            }
        }
    }
    __syncthreads();

    {
        int c2 = tid / ROWS, i2 = tid % ROWS;
#pragma unroll
        for (int g = 0; g < 14; g++) {
            if (i2 < rows)
                out[(b * OCC + c2) * NN + i0 + i2] = sm[i2][c2];
            i2 += 64; c2 += 4;
            if (i2 >= ROWS) { i2 -= ROWS; c2 += 1; }
        }
    }
}

// ---------------- launch: fork sort branch onto a second stream ----------------
extern "C" void kernel_launch(void* const* d_in, const int* in_sizes, int n_in,
                              void* d_out, int out_size) {
    const float* inp = (const float*)d_in[0];   // (16, 64, 2000)
    const float* W   = (const float*)d_in[1];   // (64, 64)
    const float* a   = (const float*)d_in[2];   // (128, 1)
    // d_in[3] = GL : unused (softmax output strictly positive -> adjacency mask is a no-op)
    float* out = (float*)d_out;                 // (16, 64, 2000)

    static cudaStream_t s2 = nullptr;
    static cudaEvent_t evA = nullptr, evB = nullptr;
    if (s2 == nullptr) {
        cudaStreamCreateWithFlags(&s2, cudaStreamNonBlocking);
        cudaEventCreateWithFlags(&evA, cudaEventDisableTiming);
        cudaEventCreateWithFlags(&evB, cudaEventDisableTiming);
    }

    // main stream: f1/f2 GEMV, then fork
    k_f<<<dim3(8, BB), 256>>>(inp, W, a);
    cudaEventRecord(evA, 0);

    // branch stream: sort + cutpoints (16 SMs), concurrent with the big GEMM
    cudaStreamWaitEvent(s2, evA, 0);
    k_sort<<<BB, 1024, 0, s2>>>();
    cudaEventRecord(evB, s2);

    // main stream: h GEMM (doesn't need the sort)
    k_h<<<dim3(25, BB), 128>>>(inp, W);

    // join, then prefix tiles + combine
    cudaStreamWaitEvent(0, evB, 0);
    k_tile<<<dim3(NT, BB), 256>>>();
    k_out <<<dim3(18, BB), 512>>>(out);
}

// round 15
// speedup vs baseline: 1.4673x; 1.0043x over previous
#include <cuda_runtime.h>
#include <math.h>

#define BB 16
#define CC 64
#define NN 2000
#define OCC 64
#define NP 2048   // padded size for bitonic sort
#define TILE 64
#define NT 32     // NT*TILE = 2048 >= NN
#define KP 2048   // prefix index space

typedef unsigned long long u64;
typedef unsigned int u32;

// ---------------- scratch (no allocations allowed) ----------------
__device__ float  g_h[BB * NN * OCC];    // h[b][n][c]
__device__ float  g_f1[BB * NN];
__device__ float  g_f2[BB * NN];
__device__ float  g_f2s[BB * NP];        // sorted f2 (ascending)
__device__ int    g_perm[BB * NP];       // sorted rank -> original j
__device__ int    g_kk[BB * NN];         // per-row cutpoint (lower_bound of -f1 in sorted f2)
__device__ float2 g_pre[BB * KP * OCC];  // within-tile excl prefix {S=exp(.01 f2)*h, B=exp(f2)*h}
__device__ float2 g_preZ[BB * KP];       // within-tile excl prefix of weights {S,B}
__device__ float2 g_ts[BB * NT * OCC];   // per-tile sums {S,B}
__device__ float2 g_tsZ[BB * NT];        // per-tile weight sums {S,B}

__device__ __forceinline__ u32 fmap(float f) {   // monotone float->u32
    u32 u = __float_as_uint(f);
    return (u & 0x80000000u) ? ~u : (u | 0x80000000u);
}

// ---------------- kernel F: f1 = x^T (W a1), f2 = x^T (W a2), straight from inp ----------------
// grid (8, 16), block 256; 250 rows per block
__global__ void k_f(const float* __restrict__ inp, const float* __restrict__ W,
                    const float* __restrict__ a) {
    __shared__ float as_[128];
    __shared__ float wa1[CC], wa2[CC];
    int b = blockIdx.y;
    int n0 = blockIdx.x * 250;
    int tid = threadIdx.x;

    if (tid < 128) as_[tid] = a[tid];
    __syncthreads();
    if (tid < 128) {   // wa1 = W @ a1, wa2 = W @ a2
        int c = tid & 63;
        const float* av = as_ + (tid >> 6) * 64;
        float s = 0.f;
#pragma unroll
        for (int oc = 0; oc < 64; oc++)
            s = fmaf(W[c * 64 + oc], av[oc], s);
        if (tid < 64) wa1[c] = s; else wa2[c] = s;
    }
    __syncthreads();

    if (tid < 250) {
        int n = n0 + tid;
        float s1 = 0.f, s2 = 0.f;
#pragma unroll 8
        for (int c = 0; c < CC; c++) {
            float xv = inp[(b * CC + c) * NN + n];   // coalesced across tid
            s1 = fmaf(xv, wa1[c], s1);
            s2 = fmaf(xv, wa2[c], s2);
        }
        g_f1[b * NN + n] = s1;
        g_f2[b * NN + n] = s2;
    }
}

// ---------------- kernel A: h = x^T W (pure GEMM) ----------------
// grid (25, 16), block 128; 80 n-columns per block; 5n x 8c register tile per thread
__global__ void k_h(const float* __restrict__ inp, const float* __restrict__ W) {
    __shared__ float xs[80][CC + 1];     // [nl][k]
    __shared__ float Ws[CC][OCC + 1];    // [k][c]
    int b = blockIdx.y;
    int n0 = blockIdx.x * 80;
    int tid = threadIdx.x;               // 0..127

    for (int t = tid; t < CC * OCC; t += 128)
        Ws[t >> 6][t & 63] = W[t];
    for (int t = tid; t < 80 * CC; t += 128) {
        int c = t / 80, nl = t % 80;
        xs[nl][c] = inp[(b * CC + c) * NN + n0 + nl];
    }
    __syncthreads();

    {
        int cg = tid & 7, ng = tid >> 3;
        int c0 = cg * 8, nl0 = ng * 5;
        float4 accA[5], accB[5];
#pragma unroll
        for (int r = 0; r < 5; r++) {
            accA[r] = make_float4(0.f, 0.f, 0.f, 0.f);
            accB[r] = make_float4(0.f, 0.f, 0.f, 0.f);
        }
#pragma unroll 4
        for (int k = 0; k < CC; k++) {
            float w0 = Ws[k][c0],     w1 = Ws[k][c0 + 1], w2 = Ws[k][c0 + 2], w3 = Ws[k][c0 + 3];
            float w4 = Ws[k][c0 + 4], w5 = Ws[k][c0 + 5], w6 = Ws[k][c0 + 6], w7 = Ws[k][c0 + 7];
#pragma unroll
            for (int r = 0; r < 5; r++) {
                float xv = xs[nl0 + r][k];
                accA[r].x = fmaf(xv, w0, accA[r].x); accA[r].y = fmaf(xv, w1, accA[r].y);
                accA[r].z = fmaf(xv, w2, accA[r].z); accA[r].w = fmaf(xv, w3, accA[r].w);
                accB[r].x = fmaf(xv, w4, accB[r].x); accB[r].y = fmaf(xv, w5, accB[r].y);
                accB[r].z = fmaf(xv, w6, accB[r].z); accB[r].w = fmaf(xv, w7, accB[r].w);
            }
        }
#pragma unroll
        for (int r = 0; r < 5; r++) {
            float4* hrow = (float4*)(g_h + (size_t)(b * NN + n0 + nl0 + r) * OCC + c0);
            hrow[0] = accA[r];
            hrow[1] = accB[r];
        }
    }
}

// ---------------- kernel C: per-batch bitonic sort (register + shfl hybrid) + search ----------------
__device__ __forceinline__ void reg_stage(u64& v0, u64& v1, int tid, int k, int jhi) {
    bool up = (((2 * tid) & k) == 0);
#pragma unroll
    for (int j = 32; j >= 2; j >>= 1) {
        if (j > jhi) continue;
        int h = j >> 1;
        u64 p0 = __shfl_xor_sync(0xffffffffu, v0, h);
        u64 p1 = __shfl_xor_sync(0xffffffffu, v1, h);
        bool takeMin = (((tid & h) == 0) == up);
        u64 lo0 = v0 < p0 ? v0 : p0, hi0 = v0 < p0 ? p0 : v0;
        u64 lo1 = v1 < p1 ? v1 : p1, hi1 = v1 < p1 ? p1 : v1;
        v0 = takeMin ? lo0 : hi0;
        v1 = takeMin ? lo1 : hi1;
    }
    if ((v0 > v1) == up) { u64 t = v0; v0 = v1; v1 = t; }
}

__global__ void k_sort() {
    __shared__ u64 s[NP];                 // 16 KB
    int b = blockIdx.x, tid = threadIdx.x;   // 1024 threads

    u64 v0, v1;
    {
        int i0 = 2 * tid, i1 = 2 * tid + 1;
        v0 = (i0 < NN) ? (((u64)fmap(g_f2[b * NN + i0]) << 32) | (u32)i0) : ~0ull;
        v1 = (i1 < NN) ? (((u64)fmap(g_f2[b * NN + i1]) << 32) | (u32)i1) : ~0ull;
    }

#pragma unroll
    for (int k = 2; k <= 64; k <<= 1)
        reg_stage(v0, v1, tid, k, k >> 1);

    s[2 * tid] = v0; s[2 * tid + 1] = v1;
    __syncthreads();

    for (int k = 128; k <= 2048; k <<= 1) {
        for (int j = k >> 1; j >= 64; j >>= 1) {
#pragma unroll
            for (int half = 0; half < 2; half++) {
                int i = tid + half * 1024;
                int ixj = i ^ j;
                if (ixj > i) {
                    bool up = ((i & k) == 0);
                    u64 a = s[i], x = s[ixj];
                    if (up ? (a > x) : (a < x)) { s[i] = x; s[ixj] = a; }
                }
            }
            __syncthreads();
        }
        v0 = s[2 * tid]; v1 = s[2 * tid + 1];
        reg_stage(v0, v1, tid, k, 32);
        s[2 * tid] = v0; s[2 * tid + 1] = v1;
        __syncthreads();
    }

    // unpack + write sorted keys/perm
#pragma unroll
    for (int half = 0; half < 2; half++) {
        int i = tid + half * 1024;
        u64 v = s[i];
        u32 hi = (u32)(v >> 32);
        hi = (hi & 0x80000000u) ? (hi ^ 0x80000000u) : ~hi;
        g_f2s[b * NP + i] = __uint_as_float(hi);
        g_perm[b * NP + i] = (int)(v & 0xffffffffu);
    }

    // per-row lower_bound of -f1 over the sorted smem keys
    for (int i = tid; i < NN; i += 1024) {
        float th = -g_f1[b * NN + i];
        u64 thp = (u64)fmap(th) << 32;
        int lo = 0, hi = NN;
        while (lo < hi) {
            int mid = (lo + hi) >> 1;
            if (s[mid] < thp) lo = mid + 1; else hi = mid;
        }
        g_kk[b * NN + i] = lo;
    }
}

// ---------------- kernel D: within-tile exclusive prefixes + tile sums ----------------
// grid (NT=32, BB), block 256: 4 segments of 16 rows x 64 channels
#define SEG 16
__global__ void k_tile() {
    __shared__ float  hs[TILE][OCC];       // 16 KB
    __shared__ float  wS[TILE], wB[TILE];
    __shared__ int    pidx[TILE];
    __shared__ float2 segsum[4][OCC];
    __shared__ float2 segoff[4][OCC];
    __shared__ float2 segsumZ[4], segoffZ[4];
    int b = blockIdx.y, t = blockIdx.x, tid = threadIdx.x;
    int r0 = t * TILE;

    if (tid < TILE) {
        int gp = r0 + tid;
        if (gp < NN) {
            float f = g_f2s[b * NP + gp];
            wS[tid] = expf(0.01f * f);
            wB[tid] = expf(f);
            pidx[tid] = g_perm[b * NP + gp];
        } else {
            wS[tid] = 0.f; wB[tid] = 0.f; pidx[tid] = 0;
        }
    }
    __syncthreads();
    // gather h rows: 64 rows x 16 float4 = 1024 loads, 4 per thread (independent)
    for (int x = tid; x < TILE * 16; x += 256) {
        int r = x >> 4, q = x & 15;
        reinterpret_cast<float4*>(hs[r])[q] =
            reinterpret_cast<const float4*>(g_h + (size_t)(b * NN + pidx[r]) * OCC)[q];
    }
    __syncthreads();

    int c = tid & 63, seg = tid >> 6;
    int rbeg = seg * SEG;

    {
        float aS = 0.f, aB = 0.f;
#pragma unroll
        for (int r = 0; r < SEG; r++) {
            int gr = rbeg + r;
            float hv = hs[gr][c];
            aS = fmaf(wS[gr], hv, aS);
            aB = fmaf(wB[gr], hv, aB);
        }
        segsum[seg][c] = make_float2(aS, aB);
    }
    if (tid < 4) {
        int rb = tid * SEG;
        float zS = 0.f, zB = 0.f;
#pragma unroll
        for (int r = 0; r < SEG; r++) { zS += wS[rb + r]; zB += wB[rb + r]; }
        segsumZ[tid] = make_float2(zS, zB);
    }
    __syncthreads();

    if (tid < 64) {
        float aS = 0.f, aB = 0.f;
#pragma unroll
        for (int s = 0; s < 4; s++) {
            segoff[s][tid] = make_float2(aS, aB);
            float2 v = segsum[s][tid];
            aS += v.x; aB += v.y;
        }
        g_ts[(b * NT + t) * OCC + tid] = make_float2(aS, aB);
    } else if (tid == 64) {
        float zS = 0.f, zB = 0.f;
#pragma unroll
        for (int s = 0; s < 4; s++) {
            segoffZ[s] = make_float2(zS, zB);
            float2 v = segsumZ[s];
            zS += v.x; zB += v.y;
        }
        g_tsZ[b * NT + t] = make_float2(zS, zB);
    }
    __syncthreads();

    {
        float2 o = segoff[seg][c];
        float aS = o.x, aB = o.y;
#pragma unroll
        for (int r = 0; r < SEG; r++) {
            int gr = rbeg + r;
            g_pre[(size_t)(b * KP + r0 + gr) * OCC + c] = make_float2(aS, aB);
            float hv = hs[gr][c];
            aS = fmaf(wS[gr], hv, aS);
            aB = fmaf(wB[gr], hv, aB);
        }
    }
    if (tid < 4) {
        int rb = tid * SEG;
        float2 o = segoffZ[tid];
        float zS = o.x, zB = o.y;
#pragma unroll
        for (int r = 0; r < SEG; r++) {
            g_preZ[b * KP + r0 + rb + r] = make_float2(zS, zB);
            zS += wS[rb + r]; zB += wB[rb + r];
        }
    }
}

// ---------------- kernel E: combine + relu + transpose, single-wave grid ----------------
// grid (18, 16), block 512; 112 rows per block (last block 96)
#define ROWS 112
__global__ void __launch_bounds__(512, 2) k_out(float* __restrict__ out) {
    __shared__ float  sm[ROWS][OCC + 1];
    __shared__ float2 to[NT + 1][OCC];    // [0]=0, then tile sums -> in-place prefix (NT=32)
    __shared__ float2 zt[NT];
    __shared__ int    kks[ROWS];
    __shared__ float4 rinfo[ROWS];

    int b = blockIdx.y;
    int i0 = blockIdx.x * ROWS;
    int rows = min(ROWS, NN - i0);
    int tid = threadIdx.x;
    int c = tid & 63, il = tid >> 6;

    // ---- phase 1: parallel staging (NT*OCC = 2048 entries, 4 per thread) ----
#pragma unroll
    for (int q = 0; q < 4; q++) {
        int x = tid + q * 512;
        int tx = x >> 6, cx = x & 63;
        to[tx + 1][cx] = g_ts[(b * NT + tx) * OCC + cx];
    }
    if (tid < 64) to[0][tid] = make_float2(0.f, 0.f);
    if (tid >= 448 && tid < 448 + NT) zt[tid - 448] = g_tsZ[b * NT + (tid - 448)];
    int rk = 0; float rf1 = 0.f; float2 rpreZ = make_float2(0.f, 0.f);
    if (tid >= 64 && tid < 64 + ROWS) {
        int r = tid - 64;
        if (r < rows) {
            rk  = g_kk[b * NN + i0 + r];
            rf1 = g_f1[b * NN + i0 + r];
            rpreZ = g_preZ[b * KP + rk];
            kks[r] = rk;
        }
    }
    __syncthreads();

    // ---- phase 2: channel to-prefix (tid<64) || per-row Z math (tid 64..64+ROWS) ----
    if (tid < 64) {
#pragma unroll
        for (int t2 = 1; t2 <= NT; t2++) {
            float2 p = to[t2 - 1][tid], v = to[t2][tid];
            to[t2][tid] = make_float2(p.x + v.x, p.y + v.y);
        }
    } else if (tid < 64 + ROWS) {
        int r = tid - 64;
        if (r < rows) {
            int t = rk >> 6;               // tile of cutpoint (TILE=64)
            float pZS = rpreZ.x, pZB = rpreZ.y, totZB = 0.f;
#pragma unroll
            for (int t2 = 0; t2 < NT; t2++) {
                float2 z = zt[t2];
                if (t2 < t) { pZS += z.x; pZB += z.y; }
                totZB += z.y;
            }
            float A  = expf(rf1);
            float aa = expf(0.01f * rf1);
            float den = A * (totZB - pZB) + aa * pZS;
            rinfo[r] = make_float4(A, aa, 1.f / den, 0.f);
        }
    }
    __syncthreads();

    // ---- phase 3: combine, 14 chunks of 8 rows; prefetch in batches of 7 ----
    {
        float totB = to[NT][c].y;
#pragma unroll
        for (int half = 0; half < 2; half++) {
            int kk[7]; float2 pv[7];
#pragma unroll
            for (int g = 0; g < 7; g++) {
                int rl = (half * 7 + g) * 8 + il;
                kk[g] = (rl < rows) ? kks[rl] : 0;
            }
#pragma unroll
            for (int g = 0; g < 7; g++)
                pv[g] = g_pre[(size_t)(b * KP + kk[g]) * OCC + c];
#pragma unroll
            for (int g = 0; g < 7; g++) {
                int rl = (half * 7 + g) * 8 + il;
                if (rl < rows) {
                    float4 ri = rinfo[rl];
                    float2 tov = to[kk[g] >> 6][c];
                    float pS = tov.x + pv[g].x;
                    float pB = tov.y + pv[g].y;
                    float num = ri.x * (totB - pB) + ri.y * pS;
                    sm[rl][c] = fmaxf(num * ri.z, 0.f);
                }
            }
        }
    }
    __syncthreads();

    // ---- phase 4: transpose-store ----
    {
        int c2 = tid / ROWS, i2 = tid % ROWS;
#pragma unroll
        for (int g = 0; g < 14; g++) {
            if (i2 < rows)
                out[(b * OCC + c2) * NN + i0 + i2] = sm[i2][c2];
            i2 += 64; c2 += 4;             // +512 = +4*112 + 64
            if (i2 >= ROWS) { i2 -= ROWS; c2 += 1; }
        }
    }
}

// ---------------- launch: fork sort branch onto a second stream ----------------
extern "C" void kernel_launch(void* const* d_in, const int* in_sizes, int n_in,
                              void* d_out, int out_size) {
    const float* inp = (const float*)d_in[0];   // (16, 64, 2000)
    const float* W   = (const float*)d_in[1];   // (64, 64)
    const float* a   = (const float*)d_in[2];   // (128, 1)
    // d_in[3] = GL : unused (softmax output strictly positive -> adjacency mask is a no-op)
    float* out = (float*)d_out;                 // (16, 64, 2000)

    static cudaStream_t s2 = nullptr;
    static cudaEvent_t evA = nullptr, evB = nullptr;
    if (s2 == nullptr) {
        cudaStreamCreateWithFlags(&s2, cudaStreamNonBlocking);
        cudaEventCreateWithFlags(&evA, cudaEventDisableTiming);
        cudaEventCreateWithFlags(&evB, cudaEventDisableTiming);
    }

    // main stream: f1/f2 GEMV, then fork
    k_f<<<dim3(8, BB), 256>>>(inp, W, a);
    cudaEventRecord(evA, 0);

    // branch stream: sort + cutpoints (16 SMs), concurrent with the big GEMM
    cudaStreamWaitEvent(s2, evA, 0);
    k_sort<<<BB, 1024, 0, s2>>>();
    cudaEventRecord(evB, s2);

    // main stream: h GEMM (doesn't need the sort)
    k_h<<<dim3(25, BB), 128>>>(inp, W);

    // join, then prefix tiles + combine
    cudaStreamWaitEvent(0, evB, 0);
    k_tile<<<dim3(NT, BB), 256>>>();
    k_out <<<dim3(18, BB), 512>>>(out);
}

// round 16
// speedup vs baseline: 1.4949x; 1.0188x over previous
#include <cuda_runtime.h>
#include <math.h>

#define BB 16
#define CC 64
#define NN 2000
#define OCC 64
#define NP 2048   // padded size for bitonic sort
#define TILE 64
#define NT 32     // NT*TILE = 2048 >= NN
#define KP 2048   // prefix index space

typedef unsigned long long u64;
typedef unsigned int u32;

// ---------------- scratch (no allocations allowed) ----------------
__device__ float  g_h[BB * NN * OCC];    // h[b][n][c]
__device__ float  g_f1[BB * NN];
__device__ float  g_f2[BB * NN];
__device__ float  g_f2s[BB * NP];        // sorted f2 (ascending)
__device__ int    g_perm[BB * NP];       // sorted rank -> original j
__device__ int    g_kk[BB * NN];         // per-row cutpoint (lower_bound of -f1 in sorted f2)
__device__ float2 g_pre[BB * KP * OCC];  // within-tile excl prefix {S=exp(.01 f2)*h, B=exp(f2)*h}
__device__ float2 g_preZ[BB * KP];       // within-tile excl prefix of weights {S,B}
__device__ float2 g_ts[BB * NT * OCC];   // per-tile sums {S,B}
__device__ float2 g_tsZ[BB * NT];        // per-tile weight sums {S,B}

__device__ __forceinline__ u32 fmap(float f) {   // monotone float->u32
    u32 u = __float_as_uint(f);
    return (u & 0x80000000u) ? ~u : (u | 0x80000000u);
}

// ---------------- kernel F: f1 = x^T (W a1), f2 = x^T (W a2), straight from inp ----------------
// grid (8, 16), block 256; 250 rows per block
__global__ void k_f(const float* __restrict__ inp, const float* __restrict__ W,
                    const float* __restrict__ a) {
    __shared__ float as_[128];
    __shared__ float wa1[CC], wa2[CC];
    int b = blockIdx.y;
    int n0 = blockIdx.x * 250;
    int tid = threadIdx.x;

    if (tid < 128) as_[tid] = a[tid];
    __syncthreads();
    if (tid < 128) {   // wa1 = W @ a1, wa2 = W @ a2
        int c = tid & 63;
        const float* av = as_ + (tid >> 6) * 64;
        float s = 0.f;
#pragma unroll
        for (int oc = 0; oc < 64; oc++)
            s = fmaf(W[c * 64 + oc], av[oc], s);
        if (tid < 64) wa1[c] = s; else wa2[c] = s;
    }
    __syncthreads();

    if (tid < 250) {
        int n = n0 + tid;
        float s1 = 0.f, s2 = 0.f;
#pragma unroll 8
        for (int c = 0; c < CC; c++) {
            float xv = inp[(b * CC + c) * NN + n];   // coalesced across tid
            s1 = fmaf(xv, wa1[c], s1);
            s2 = fmaf(xv, wa2[c], s2);
        }
        g_f1[b * NN + n] = s1;
        g_f2[b * NN + n] = s2;
    }
}

// ---------------- kernel A: h = x^T W (pure GEMM) ----------------
// grid (25, 16), block 128; 80 n-columns per block; 5n x 8c register tile per thread
__global__ void k_h(const float* __restrict__ inp, const float* __restrict__ W) {
    __shared__ float xs[80][CC + 1];     // [nl][k]
    __shared__ float Ws[CC][OCC + 1];    // [k][c]
    int b = blockIdx.y;
    int n0 = blockIdx.x * 80;
    int tid = threadIdx.x;               // 0..127

    for (int t = tid; t < CC * OCC; t += 128)
        Ws[t >> 6][t & 63] = W[t];
    for (int t = tid; t < 80 * CC; t += 128) {
        int c = t / 80, nl = t % 80;
        xs[nl][c] = inp[(b * CC + c) * NN + n0 + nl];
    }
    __syncthreads();

    {
        int cg = tid & 7, ng = tid >> 3;
        int c0 = cg * 8, nl0 = ng * 5;
        float4 accA[5], accB[5];
#pragma unroll
        for (int r = 0; r < 5; r++) {
            accA[r] = make_float4(0.f, 0.f, 0.f, 0.f);
            accB[r] = make_float4(0.f, 0.f, 0.f, 0.f);
        }
#pragma unroll 4
        for (int k = 0; k < CC; k++) {
            float w0 = Ws[k][c0],     w1 = Ws[k][c0 + 1], w2 = Ws[k][c0 + 2], w3 = Ws[k][c0 + 3];
            float w4 = Ws[k][c0 + 4], w5 = Ws[k][c0 + 5], w6 = Ws[k][c0 + 6], w7 = Ws[k][c0 + 7];
#pragma unroll
            for (int r = 0; r < 5; r++) {
                float xv = xs[nl0 + r][k];
                accA[r].x = fmaf(xv, w0, accA[r].x); accA[r].y = fmaf(xv, w1, accA[r].y);
                accA[r].z = fmaf(xv, w2, accA[r].z); accA[r].w = fmaf(xv, w3, accA[r].w);
                accB[r].x = fmaf(xv, w4, accB[r].x); accB[r].y = fmaf(xv, w5, accB[r].y);
                accB[r].z = fmaf(xv, w6, accB[r].z); accB[r].w = fmaf(xv, w7, accB[r].w);
            }
        }
#pragma unroll
        for (int r = 0; r < 5; r++) {
            float4* hrow = (float4*)(g_h + (size_t)(b * NN + n0 + nl0 + r) * OCC + c0);
            hrow[0] = accA[r];
            hrow[1] = accB[r];
        }
    }
}

// ---------------- kernel C: per-batch bitonic sort (register + shfl hybrid) + search ----------------
__device__ __forceinline__ void reg_stage(u64& v0, u64& v1, int tid, int k, int jhi) {
    bool up = (((2 * tid) & k) == 0);
#pragma unroll
    for (int j = 32; j >= 2; j >>= 1) {
        if (j > jhi) continue;
        int h = j >> 1;
        u64 p0 = __shfl_xor_sync(0xffffffffu, v0, h);
        u64 p1 = __shfl_xor_sync(0xffffffffu, v1, h);
        bool takeMin = (((tid & h) == 0) == up);
        u64 lo0 = v0 < p0 ? v0 : p0, hi0 = v0 < p0 ? p0 : v0;
        u64 lo1 = v1 < p1 ? v1 : p1, hi1 = v1 < p1 ? p1 : v1;
        v0 = takeMin ? lo0 : hi0;
        v1 = takeMin ? lo1 : hi1;
    }
    if ((v0 > v1) == up) { u64 t = v0; v0 = v1; v1 = t; }
}

__global__ void k_sort() {
    __shared__ u64 s[NP];                 // 16 KB
    int b = blockIdx.x, tid = threadIdx.x;   // 1024 threads

    u64 v0, v1;
    {
        int i0 = 2 * tid, i1 = 2 * tid + 1;
        v0 = (i0 < NN) ? (((u64)fmap(g_f2[b * NN + i0]) << 32) | (u32)i0) : ~0ull;
        v1 = (i1 < NN) ? (((u64)fmap(g_f2[b * NN + i1]) << 32) | (u32)i1) : ~0ull;
    }

#pragma unroll
    for (int k = 2; k <= 64; k <<= 1)
        reg_stage(v0, v1, tid, k, k >> 1);

    s[2 * tid] = v0; s[2 * tid + 1] = v1;
    __syncthreads();

    for (int k = 128; k <= 2048; k <<= 1) {
        for (int j = k >> 1; j >= 64; j >>= 1) {
#pragma unroll
            for (int half = 0; half < 2; half++) {
                int i = tid + half * 1024;
                int ixj = i ^ j;
                if (ixj > i) {
                    bool up = ((i & k) == 0);
                    u64 a = s[i], x = s[ixj];
                    if (up ? (a > x) : (a < x)) { s[i] = x; s[ixj] = a; }
                }
            }
            __syncthreads();
        }
        v0 = s[2 * tid]; v1 = s[2 * tid + 1];
        reg_stage(v0, v1, tid, k, 32);
        s[2 * tid] = v0; s[2 * tid + 1] = v1;
        __syncthreads();
    }

    // unpack + write sorted keys/perm
#pragma unroll
    for (int half = 0; half < 2; half++) {
        int i = tid + half * 1024;
        u64 v = s[i];
        u32 hi = (u32)(v >> 32);
        hi = (hi & 0x80000000u) ? (hi ^ 0x80000000u) : ~hi;
        g_f2s[b * NP + i] = __uint_as_float(hi);
        g_perm[b * NP + i] = (int)(v & 0xffffffffu);
    }

    // per-row lower_bound of -f1 over the sorted smem keys
    for (int i = tid; i < NN; i += 1024) {
        float th = -g_f1[b * NN + i];
        u64 thp = (u64)fmap(th) << 32;
        int lo = 0, hi = NN;
        while (lo < hi) {
            int mid = (lo + hi) >> 1;
            if (s[mid] < thp) lo = mid + 1; else hi = mid;
        }
        g_kk[b * NN + i] = lo;
    }
}

// ---------------- kernel D: within-tile exclusive prefixes + tile sums ----------------
// grid (NT=32, BB, 2), block 128: z splits channels; 4 segments of 16 rows x 32 channels
#define SEG 16
__global__ void k_tile() {
    __shared__ float  hs[TILE][32];        // 8 KB (half channel width)
    __shared__ float  wS[TILE], wB[TILE];
    __shared__ int    pidx[TILE];
    __shared__ float2 segsum[4][32];
    __shared__ float2 segoff[4][32];
    __shared__ float2 segsumZ[4], segoffZ[4];
    int b = blockIdx.y, t = blockIdx.x, z = blockIdx.z, tid = threadIdx.x;
    int r0 = t * TILE;
    int c0 = z * 32;

    if (tid < TILE) {
        int gp = r0 + tid;
        if (gp < NN) {
            float f = g_f2s[b * NP + gp];
            wS[tid] = expf(0.01f * f);
            wB[tid] = expf(f);
            pidx[tid] = g_perm[b * NP + gp];
        } else {
            wS[tid] = 0.f; wB[tid] = 0.f; pidx[tid] = 0;
        }
    }
    __syncthreads();
    // gather half-width h rows: 64 rows x 8 float4 = 512 loads, 4 per thread
    for (int x = tid; x < TILE * 8; x += 128) {
        int r = x >> 3, q = x & 7;
        reinterpret_cast<float4*>(hs[r])[q] =
            reinterpret_cast<const float4*>(g_h + (size_t)(b * NN + pidx[r]) * OCC + c0)[q];
    }
    __syncthreads();

    int c = tid & 31, seg = tid >> 5;
    int rbeg = seg * SEG;

    {
        float aS = 0.f, aB = 0.f;
#pragma unroll
        for (int r = 0; r < SEG; r++) {
            int gr = rbeg + r;
            float hv = hs[gr][c];
            aS = fmaf(wS[gr], hv, aS);
            aB = fmaf(wB[gr], hv, aB);
        }
        segsum[seg][c] = make_float2(aS, aB);
    }
    if (z == 0 && tid < 4) {
        int rb = tid * SEG;
        float zS = 0.f, zB = 0.f;
#pragma unroll
        for (int r = 0; r < SEG; r++) { zS += wS[rb + r]; zB += wB[rb + r]; }
        segsumZ[tid] = make_float2(zS, zB);
    }
    __syncthreads();

    if (tid < 32) {
        float aS = 0.f, aB = 0.f;
#pragma unroll
        for (int s = 0; s < 4; s++) {
            segoff[s][tid] = make_float2(aS, aB);
            float2 v = segsum[s][tid];
            aS += v.x; aB += v.y;
        }
        g_ts[(b * NT + t) * OCC + c0 + tid] = make_float2(aS, aB);
    } else if (z == 0 && tid == 32) {
        float zS = 0.f, zB = 0.f;
#pragma unroll
        for (int s = 0; s < 4; s++) {
            segoffZ[s] = make_float2(zS, zB);
            float2 v = segsumZ[s];
            zS += v.x; zB += v.y;
        }
        g_tsZ[b * NT + t] = make_float2(zS, zB);
    }
    __syncthreads();

    {
        float2 o = segoff[seg][c];
        float aS = o.x, aB = o.y;
#pragma unroll
        for (int r = 0; r < SEG; r++) {
            int gr = rbeg + r;
            g_pre[(size_t)(b * KP + r0 + gr) * OCC + c0 + c] = make_float2(aS, aB);
            float hv = hs[gr][c];
            aS = fmaf(wS[gr], hv, aS);
            aB = fmaf(wB[gr], hv, aB);
        }
    }
    if (z == 0 && tid < 4) {
        int rb = tid * SEG;
        float2 o = segoffZ[tid];
        float zS = o.x, zB = o.y;
#pragma unroll
        for (int r = 0; r < SEG; r++) {
            g_preZ[b * KP + r0 + rb + r] = make_float2(zS, zB);
            zS += wS[rb + r]; zB += wB[rb + r];
        }
    }
}

// ---------------- kernel E: combine + relu + transpose, single-wave grid ----------------
// grid (18, 16), block 512; 112 rows per block (last block 96)
#define ROWS 112
__global__ void __launch_bounds__(512, 2) k_out(float* __restrict__ out) {
    __shared__ float  sm[ROWS][OCC + 1];
    __shared__ float2 to[NT + 1][OCC];    // [0]=0, then tile sums -> in-place prefix (NT=32)
    __shared__ float2 zt[NT];
    __shared__ int    kks[ROWS];
    __shared__ float4 rinfo[ROWS];

    int b = blockIdx.y;
    int i0 = blockIdx.x * ROWS;
    int rows = min(ROWS, NN - i0);
    int tid = threadIdx.x;
    int c = tid & 63, il = tid >> 6;

    // ---- phase 1: parallel staging (NT*OCC = 2048 entries, 4 per thread) ----
#pragma unroll
    for (int q = 0; q < 4; q++) {
        int x = tid + q * 512;
        int tx = x >> 6, cx = x & 63;
        to[tx + 1][cx] = g_ts[(b * NT + tx) * OCC + cx];
    }
    if (tid < 64) to[0][tid] = make_float2(0.f, 0.f);
    if (tid >= 448 && tid < 448 + NT) zt[tid - 448] = g_tsZ[b * NT + (tid - 448)];
    int rk = 0; float rf1 = 0.f; float2 rpreZ = make_float2(0.f, 0.f);
    if (tid >= 64 && tid < 64 + ROWS) {
        int r = tid - 64;
        if (r < rows) {
            rk  = g_kk[b * NN + i0 + r];
            rf1 = g_f1[b * NN + i0 + r];
            rpreZ = g_preZ[b * KP + rk];
            kks[r] = rk;
        }
    }
    __syncthreads();

    // ---- phase 2: channel to-prefix (tid<64) || per-row Z math (tid 64..64+ROWS) ----
    if (tid < 64) {
#pragma unroll
        for (int t2 = 1; t2 <= NT; t2++) {
            float2 p = to[t2 - 1][tid], v = to[t2][tid];
            to[t2][tid] = make_float2(p.x + v.x, p.y + v.y);
        }
    } else if (tid < 64 + ROWS) {
        int r = tid - 64;
        if (r < rows) {
            int t = rk >> 6;               // tile of cutpoint (TILE=64)
            float pZS = rpreZ.x, pZB = rpreZ.y, totZB = 0.f;
#pragma unroll
            for (int t2 = 0; t2 < NT; t2++) {
                float2 z = zt[t2];
                if (t2 < t) { pZS += z.x; pZB += z.y; }
                totZB += z.y;
            }
            float A  = expf(rf1);
            float aa = expf(0.01f * rf1);
            float den = A * (totZB - pZB) + aa * pZS;
            rinfo[r] = make_float4(A, aa, 1.f / den, 0.f);
        }
    }
    __syncthreads();

    // ---- phase 3: combine, 14 chunks of 8 rows; prefetch in batches of 7 ----
    {
        float totB = to[NT][c].y;
#pragma unroll
        for (int half = 0; half < 2; half++) {
            int kk[7]; float2 pv[7];
#pragma unroll
            for (int g = 0; g < 7; g++) {
                int rl = (half * 7 + g) * 8 + il;
                kk[g] = (rl < rows) ? kks[rl] : 0;
            }
#pragma unroll
            for (int g = 0; g < 7; g++)
                pv[g] = g_pre[(size_t)(b * KP + kk[g]) * OCC + c];
#pragma unroll
            for (int g = 0; g < 7; g++) {
                int rl = (half * 7 + g) * 8 + il;
                if (rl < rows) {
                    float4 ri = rinfo[rl];
                    float2 tov = to[kk[g] >> 6][c];
                    float pS = tov.x + pv[g].x;
                    float pB = tov.y + pv[g].y;
                    float num = ri.x * (totB - pB) + ri.y * pS;
                    sm[rl][c] = fmaxf(num * ri.z, 0.f);
                }
            }
        }
    }
    __syncthreads();

    // ---- phase 4: transpose-store ----
    {
        int c2 = tid / ROWS, i2 = tid % ROWS;
#pragma unroll
        for (int g = 0; g < 14; g++) {
            if (i2 < rows)
                out[(b * OCC + c2) * NN + i0 + i2] = sm[i2][c2];
            i2 += 64; c2 += 4;             // +512 = +4*112 + 64
            if (i2 >= ROWS) { i2 -= ROWS; c2 += 1; }
        }
    }
}

// ---------------- launch: fork sort branch onto a second stream ----------------
extern "C" void kernel_launch(void* const* d_in, const int* in_sizes, int n_in,
                              void* d_out, int out_size) {
    const float* inp = (const float*)d_in[0];   // (16, 64, 2000)
    const float* W   = (const float*)d_in[1];   // (64, 64)
    const float* a   = (const float*)d_in[2];   // (128, 1)
    // d_in[3] = GL : unused (softmax output strictly positive -> adjacency mask is a no-op)
    float* out = (float*)d_out;                 // (16, 64, 2000)

    static cudaStream_t s2 = nullptr;
    static cudaEvent_t evA = nullptr, evB = nullptr;
    if (s2 == nullptr) {
        cudaStreamCreateWithFlags(&s2, cudaStreamNonBlocking);
        cudaEventCreateWithFlags(&evA, cudaEventDisableTiming);
        cudaEventCreateWithFlags(&evB, cudaEventDisableTiming);
    }

    // main stream: f1/f2 GEMV, then fork
    k_f<<<dim3(8, BB), 256>>>(inp, W, a);
    cudaEventRecord(evA, 0);

    // branch stream: sort + cutpoints (16 SMs), concurrent with the big GEMM
    cudaStreamWaitEvent(s2, evA, 0);
    k_sort<<<BB, 1024, 0, s2>>>();
    cudaEventRecord(evB, s2);

    // main stream: h GEMM (doesn't need the sort)
    k_h<<<dim3(25, BB), 128>>>(inp, W);

    // join, then prefix tiles + combine
    cudaStreamWaitEvent(0, evB, 0);
    k_tile<<<dim3(NT, BB, 2), 128>>>();
    k_out <<<dim3(18, BB), 512>>>(out);
}

// round 17
// speedup vs baseline: 1.5372x; 1.0283x over previous
#include <cuda_runtime.h>
#include <math.h>

#define BB 16
#define CC 64
#define NN 2000
#define OCC 64
#define NP 2048   // padded size for bitonic sort
#define TILE 64
#define NT 32     // NT*TILE = 2048 >= NN
#define KP 2048   // prefix index space

typedef unsigned long long u64;
typedef unsigned int u32;

// ---------------- scratch (no allocations allowed) ----------------
__device__ float  g_h[BB * NN * OCC];    // h[b][n][c]
__device__ float  g_f1[BB * NN];
__device__ float  g_f2[BB * NN];
__device__ float  g_f2s[BB * NP];        // sorted f2 (ascending)
__device__ int    g_perm[BB * NP];       // sorted rank -> original j
__device__ int    g_kk[BB * NN];         // per-row cutpoint (lower_bound of -f1 in sorted f2)
__device__ float2 g_pre[BB * KP * OCC];  // within-tile excl prefix {S=exp(.01 f2)*h, B=exp(f2)*h}
__device__ float2 g_preZ[BB * KP];       // within-tile excl prefix of weights {S,B}
__device__ float2 g_ts[BB * NT * OCC];   // per-tile sums {S,B}
__device__ float2 g_tsZ[BB * NT];        // per-tile weight sums {S,B}

__device__ __forceinline__ u32 fmap(float f) {   // monotone float->u32
    u32 u = __float_as_uint(f);
    return (u & 0x80000000u) ? ~u : (u | 0x80000000u);
}

// ---------------- kernel F: f1 = x^T (W a1), f2 = x^T (W a2), straight from inp ----------------
// grid (8, 16), block 256; 250 rows per block
__global__ void k_f(const float* __restrict__ inp, const float* __restrict__ W,
                    const float* __restrict__ a) {
    __shared__ float as_[128];
    __shared__ float wa1[CC], wa2[CC];
    int b = blockIdx.y;
    int n0 = blockIdx.x * 250;
    int tid = threadIdx.x;

    if (tid < 128) as_[tid] = a[tid];
    __syncthreads();
    if (tid < 128) {   // wa1 = W @ a1, wa2 = W @ a2
        int c = tid & 63;
        const float* av = as_ + (tid >> 6) * 64;
        float s = 0.f;
#pragma unroll
        for (int oc = 0; oc < 64; oc++)
            s = fmaf(W[c * 64 + oc], av[oc], s);
        if (tid < 64) wa1[c] = s; else wa2[c] = s;
    }
    __syncthreads();

    if (tid < 250) {
        int n = n0 + tid;
        float s1 = 0.f, s2 = 0.f;
#pragma unroll 8
        for (int c = 0; c < CC; c++) {
            float xv = inp[(b * CC + c) * NN + n];   // coalesced across tid
            s1 = fmaf(xv, wa1[c], s1);
            s2 = fmaf(xv, wa2[c], s2);
        }
        g_f1[b * NN + n] = s1;
        g_f2[b * NN + n] = s2;
    }
}

// ---------------- kernel A: h = x^T W (pure GEMM) ----------------
// grid (25, 16), block 128; 80 n-columns per block; 5n x 8c register tile per thread
__global__ void k_h(const float* __restrict__ inp, const float* __restrict__ W) {
    __shared__ float xs[80][CC + 1];     // [nl][k]
    __shared__ float Ws[CC][OCC + 1];    // [k][c]
    int b = blockIdx.y;
    int n0 = blockIdx.x * 80;
    int tid = threadIdx.x;               // 0..127

    for (int t = tid; t < CC * OCC; t += 128)
        Ws[t >> 6][t & 63] = W[t];
    for (int t = tid; t < 80 * CC; t += 128) {
        int c = t / 80, nl = t % 80;
        xs[nl][c] = inp[(b * CC + c) * NN + n0 + nl];
    }
    __syncthreads();

    {
        int cg = tid & 7, ng = tid >> 3;
        int c0 = cg * 8, nl0 = ng * 5;
        float4 accA[5], accB[5];
#pragma unroll
        for (int r = 0; r < 5; r++) {
            accA[r] = make_float4(0.f, 0.f, 0.f, 0.f);
            accB[r] = make_float4(0.f, 0.f, 0.f, 0.f);
        }
#pragma unroll 4
        for (int k = 0; k < CC; k++) {
            float w0 = Ws[k][c0],     w1 = Ws[k][c0 + 1], w2 = Ws[k][c0 + 2], w3 = Ws[k][c0 + 3];
            float w4 = Ws[k][c0 + 4], w5 = Ws[k][c0 + 5], w6 = Ws[k][c0 + 6], w7 = Ws[k][c0 + 7];
#pragma unroll
            for (int r = 0; r < 5; r++) {
                float xv = xs[nl0 + r][k];
                accA[r].x = fmaf(xv, w0, accA[r].x); accA[r].y = fmaf(xv, w1, accA[r].y);
                accA[r].z = fmaf(xv, w2, accA[r].z); accA[r].w = fmaf(xv, w3, accA[r].w);
                accB[r].x = fmaf(xv, w4, accB[r].x); accB[r].y = fmaf(xv, w5, accB[r].y);
                accB[r].z = fmaf(xv, w6, accB[r].z); accB[r].w = fmaf(xv, w7, accB[r].w);
            }
        }
#pragma unroll
        for (int r = 0; r < 5; r++) {
            float4* hrow = (float4*)(g_h + (size_t)(b * NN + n0 + nl0 + r) * OCC + c0);
            hrow[0] = accA[r];
            hrow[1] = accB[r];
        }
    }
}

// ---------------- kernel C: per-batch bitonic sort (register + shfl hybrid) + search ----------------
__device__ __forceinline__ void reg_stage(u64& v0, u64& v1, int tid, int k, int jhi) {
    bool up = (((2 * tid) & k) == 0);
#pragma unroll
    for (int j = 32; j >= 2; j >>= 1) {
        if (j > jhi) continue;
        int h = j >> 1;
        u64 p0 = __shfl_xor_sync(0xffffffffu, v0, h);
        u64 p1 = __shfl_xor_sync(0xffffffffu, v1, h);
        bool takeMin = (((tid & h) == 0) == up);
        u64 lo0 = v0 < p0 ? v0 : p0, hi0 = v0 < p0 ? p0 : v0;
        u64 lo1 = v1 < p1 ? v1 : p1, hi1 = v1 < p1 ? p1 : v1;
        v0 = takeMin ? lo0 : hi0;
        v1 = takeMin ? lo1 : hi1;
    }
    if ((v0 > v1) == up) { u64 t = v0; v0 = v1; v1 = t; }
}

__global__ void k_sort() {
    __shared__ u64 s[NP];                 // 16 KB
    int b = blockIdx.x, tid = threadIdx.x;   // 1024 threads

    u64 v0, v1;
    {
        int i0 = 2 * tid, i1 = 2 * tid + 1;
        v0 = (i0 < NN) ? (((u64)fmap(g_f2[b * NN + i0]) << 32) | (u32)i0) : ~0ull;
        v1 = (i1 < NN) ? (((u64)fmap(g_f2[b * NN + i1]) << 32) | (u32)i1) : ~0ull;
    }

#pragma unroll
    for (int k = 2; k <= 64; k <<= 1)
        reg_stage(v0, v1, tid, k, k >> 1);

    s[2 * tid] = v0; s[2 * tid + 1] = v1;
    __syncthreads();

    for (int k = 128; k <= 2048; k <<= 1) {
        for (int j = k >> 1; j >= 64; j >>= 1) {
#pragma unroll
            for (int half = 0; half < 2; half++) {
                int i = tid + half * 1024;
                int ixj = i ^ j;
                if (ixj > i) {
                    bool up = ((i & k) == 0);
                    u64 a = s[i], x = s[ixj];
                    if (up ? (a > x) : (a < x)) { s[i] = x; s[ixj] = a; }
                }
            }
            __syncthreads();
        }
        v0 = s[2 * tid]; v1 = s[2 * tid + 1];
        reg_stage(v0, v1, tid, k, 32);
        s[2 * tid] = v0; s[2 * tid + 1] = v1;
        __syncthreads();
    }

    // unpack + write sorted keys/perm
#pragma unroll
    for (int half = 0; half < 2; half++) {
        int i = tid + half * 1024;
        u64 v = s[i];
        u32 hi = (u32)(v >> 32);
        hi = (hi & 0x80000000u) ? (hi ^ 0x80000000u) : ~hi;
        g_f2s[b * NP + i] = __uint_as_float(hi);
        g_perm[b * NP + i] = (int)(v & 0xffffffffu);
    }

    // per-row lower_bound of -f1 over the sorted smem keys
    for (int i = tid; i < NN; i += 1024) {
        float th = -g_f1[b * NN + i];
        u64 thp = (u64)fmap(th) << 32;
        int lo = 0, hi = NN;
        while (lo < hi) {
            int mid = (lo + hi) >> 1;
            if (s[mid] < thp) lo = mid + 1; else hi = mid;
        }
        g_kk[b * NN + i] = lo;
    }
}

// ---------------- kernel D: within-tile exclusive prefixes + tile sums ----------------
// grid (NT=32, BB, 2), block 256: z splits channels; 8 segments of 8 rows x 32 channels
#define SEG 8
#define NSEG 8
__global__ void k_tile() {
    __shared__ float  hs[TILE][32];        // 8 KB (half channel width)
    __shared__ float  wS[TILE], wB[TILE];
    __shared__ int    pidx[TILE];
    __shared__ float2 segsum[NSEG][32];
    __shared__ float2 segoff[NSEG][32];
    __shared__ float2 segsumZ[NSEG], segoffZ[NSEG];
    int b = blockIdx.y, t = blockIdx.x, z = blockIdx.z, tid = threadIdx.x;
    int r0 = t * TILE;
    int c0 = z * 32;

    if (tid < TILE) {
        int gp = r0 + tid;
        if (gp < NN) {
            float f = g_f2s[b * NP + gp];
            wS[tid] = expf(0.01f * f);
            wB[tid] = expf(f);
            pidx[tid] = g_perm[b * NP + gp];
        } else {
            wS[tid] = 0.f; wB[tid] = 0.f; pidx[tid] = 0;
        }
    }
    __syncthreads();
    // gather half-width h rows: 64 rows x 8 float4 = 512 loads, 2 per thread
    for (int x = tid; x < TILE * 8; x += 256) {
        int r = x >> 3, q = x & 7;
        reinterpret_cast<float4*>(hs[r])[q] =
            reinterpret_cast<const float4*>(g_h + (size_t)(b * NN + pidx[r]) * OCC + c0)[q];
    }
    __syncthreads();

    int c = tid & 31, seg = tid >> 5;      // seg 0..7
    int rbeg = seg * SEG;

    {
        float aS = 0.f, aB = 0.f;
#pragma unroll
        for (int r = 0; r < SEG; r++) {
            int gr = rbeg + r;
            float hv = hs[gr][c];
            aS = fmaf(wS[gr], hv, aS);
            aB = fmaf(wB[gr], hv, aB);
        }
        segsum[seg][c] = make_float2(aS, aB);
    }
    if (z == 0 && tid < NSEG) {
        int rb = tid * SEG;
        float zS = 0.f, zB = 0.f;
#pragma unroll
        for (int r = 0; r < SEG; r++) { zS += wS[rb + r]; zB += wB[rb + r]; }
        segsumZ[tid] = make_float2(zS, zB);
    }
    __syncthreads();

    if (tid < 32) {
        float aS = 0.f, aB = 0.f;
#pragma unroll
        for (int s = 0; s < NSEG; s++) {
            segoff[s][tid] = make_float2(aS, aB);
            float2 v = segsum[s][tid];
            aS += v.x; aB += v.y;
        }
        g_ts[(b * NT + t) * OCC + c0 + tid] = make_float2(aS, aB);
    } else if (z == 0 && tid == 32) {
        float zS = 0.f, zB = 0.f;
#pragma unroll
        for (int s = 0; s < NSEG; s++) {
            segoffZ[s] = make_float2(zS, zB);
            float2 v = segsumZ[s];
            zS += v.x; zB += v.y;
        }
        g_tsZ[b * NT + t] = make_float2(zS, zB);
    }
    __syncthreads();

    {
        float2 o = segoff[seg][c];
        float aS = o.x, aB = o.y;
#pragma unroll
        for (int r = 0; r < SEG; r++) {
            int gr = rbeg + r;
            g_pre[(size_t)(b * KP + r0 + gr) * OCC + c0 + c] = make_float2(aS, aB);
            float hv = hs[gr][c];
            aS = fmaf(wS[gr], hv, aS);
            aB = fmaf(wB[gr], hv, aB);
        }
    }
    if (z == 0 && tid < NSEG) {
        int rb = tid * SEG;
        float2 o = segoffZ[tid];
        float zS = o.x, zB = o.y;
#pragma unroll
        for (int r = 0; r < SEG; r++) {
            g_preZ[b * KP + r0 + rb + r] = make_float2(zS, zB);
            zS += wS[rb + r]; zB += wB[rb + r];
        }
    }
}

// ---------------- kernel E: combine + relu + transpose, single-wave grid ----------------
// grid (18, 16), block 512; 112 rows per block (last block 96)
#define ROWS 112
__global__ void __launch_bounds__(512, 2) k_out(float* __restrict__ out) {
    __shared__ float  sm[ROWS][OCC + 1];
    __shared__ float2 to[NT + 1][OCC];    // [0]=0, then tile sums -> in-place prefix (NT=32)
    __shared__ float2 zt[NT];
    __shared__ int    kks[ROWS];
    __shared__ float4 rinfo[ROWS];

    int b = blockIdx.y;
    int i0 = blockIdx.x * ROWS;
    int rows = min(ROWS, NN - i0);
    int tid = threadIdx.x;
    int c = tid & 63, il = tid >> 6;

    // ---- phase 1: parallel staging (NT*OCC = 2048 entries, 4 per thread) ----
#pragma unroll
    for (int q = 0; q < 4; q++) {
        int x = tid + q * 512;
        int tx = x >> 6, cx = x & 63;
        to[tx + 1][cx] = g_ts[(b * NT + tx) * OCC + cx];
    }
    if (tid < 64) to[0][tid] = make_float2(0.f, 0.f);
    if (tid >= 448 && tid < 448 + NT) zt[tid - 448] = g_tsZ[b * NT + (tid - 448)];
    int rk = 0; float rf1 = 0.f; float2 rpreZ = make_float2(0.f, 0.f);
    if (tid >= 64 && tid < 64 + ROWS) {
        int r = tid - 64;
        if (r < rows) {
            rk  = g_kk[b * NN + i0 + r];
            rf1 = g_f1[b * NN + i0 + r];
            rpreZ = g_preZ[b * KP + rk];
            kks[r] = rk;
        }
    }
    __syncthreads();

    // ---- phase 2: channel to-prefix (tid<64) || per-row Z math (tid 64..64+ROWS) ----
    if (tid < 64) {
#pragma unroll
        for (int t2 = 1; t2 <= NT; t2++) {
            float2 p = to[t2 - 1][tid], v = to[t2][tid];
            to[t2][tid] = make_float2(p.x + v.x, p.y + v.y);
        }
    } else if (tid < 64 + ROWS) {
        int r = tid - 64;
        if (r < rows) {
            int t = rk >> 6;               // tile of cutpoint (TILE=64)
            float pZS = rpreZ.x, pZB = rpreZ.y, totZB = 0.f;
#pragma unroll
            for (int t2 = 0; t2 < NT; t2++) {
                float2 z = zt[t2];
                if (t2 < t) { pZS += z.x; pZB += z.y; }
                totZB += z.y;
            }
            float A  = expf(rf1);
            float aa = expf(0.01f * rf1);
            float den = A * (totZB - pZB) + aa * pZS;
            rinfo[r] = make_float4(A, aa, 1.f / den, 0.f);
        }
    }
    __syncthreads();

    // ---- phase 3: combine, 14 chunks of 8 rows; prefetch in batches of 7 ----
    {
        float totB = to[NT][c].y;
#pragma unroll
        for (int half = 0; half < 2; half++) {
            int kk[7]; float2 pv[7];
#pragma unroll
            for (int g = 0; g < 7; g++) {
                int rl = (half * 7 + g) * 8 + il;
                kk[g] = (rl < rows) ? kks[rl] : 0;
            }
#pragma unroll
            for (int g = 0; g < 7; g++)
                pv[g] = g_pre[(size_t)(b * KP + kk[g]) * OCC + c];
#pragma unroll
            for (int g = 0; g < 7; g++) {
                int rl = (half * 7 + g) * 8 + il;
                if (rl < rows) {
                    float4 ri = rinfo[rl];
                    float2 tov = to[kk[g] >> 6][c];
                    float pS = tov.x + pv[g].x;
                    float pB = tov.y + pv[g].y;
                    float num = ri.x * (totB - pB) + ri.y * pS;
                    sm[rl][c] = fmaxf(num * ri.z, 0.f);
                }
            }
        }
    }
    __syncthreads();

    // ---- phase 4: transpose-store ----
    {
        int c2 = tid / ROWS, i2 = tid % ROWS;
#pragma unroll
        for (int g = 0; g < 14; g++) {
            if (i2 < rows)
                out[(b * OCC + c2) * NN + i0 + i2] = sm[i2][c2];
            i2 += 64; c2 += 4;             // +512 = +4*112 + 64
            if (i2 >= ROWS) { i2 -= ROWS; c2 += 1; }
        }
    }
}

// ---------------- launch: fork sort branch onto a second stream ----------------
extern "C" void kernel_launch(void* const* d_in, const int* in_sizes, int n_in,
                              void* d_out, int out_size) {
    const float* inp = (const float*)d_in[0];   // (16, 64, 2000)
    const float* W   = (const float*)d_in[1];   // (64, 64)
    const float* a   = (const float*)d_in[2];   // (128, 1)
    // d_in[3] = GL : unused (softmax output strictly positive -> adjacency mask is a no-op)
    float* out = (float*)d_out;                 // (16, 64, 2000)

    static cudaStream_t s2 = nullptr;
    static cudaEvent_t evA = nullptr, evB = nullptr;
    if (s2 == nullptr) {
        cudaStreamCreateWithFlags(&s2, cudaStreamNonBlocking);
        cudaEventCreateWithFlags(&evA, cudaEventDisableTiming);
        cudaEventCreateWithFlags(&evB, cudaEventDisableTiming);
    }

    // main stream: f1/f2 GEMV, then fork
    k_f<<<dim3(8, BB), 256>>>(inp, W, a);
    cudaEventRecord(evA, 0);

    // branch stream: sort + cutpoints (16 SMs), concurrent with the big GEMM
    cudaStreamWaitEvent(s2, evA, 0);
    k_sort<<<BB, 1024, 0, s2>>>();
    cudaEventRecord(evB, s2);

    // main stream: h GEMM (doesn't need the sort)
    k_h<<<dim3(25, BB), 128>>>(inp, W);

    // join, then prefix tiles + combine
    cudaStreamWaitEvent(0, evB, 0);
    k_tile<<<dim3(NT, BB, 2), 256>>>();
    k_out <<<dim3(18, BB), 512>>>(out);
}